// round 1
// baseline (speedup 1.0000x reference)
#include <cuda_runtime.h>
#include <math.h>

#define NS    32768
#define DD    32
#define SPLITD 16
#define D2    16
#define BINSN 16
#define HID   320
#define POUT  1008
#define LOG2PI_F 1.8378770664093453f

// ---------------- scratch (device globals: no runtime allocation) ----------------
__device__ float g_z[NS * DD];       // current latent, updated in place
__device__ float g_H1[NS * HID];
__device__ float g_H2[NS * HID];
__device__ float g_P[(size_t)NS * POUT];
__device__ float g_ladj[NS * SPLITD];
__device__ float g_lpaff;

// ---------------- small kernels ----------------
__global__ void k_lpaff(const float* __restrict__ stds) {
    int d = threadIdx.x;  // 32 threads
    float v = logf(10.0f * stds[d]);
#pragma unroll
    for (int o = 16; o > 0; o >>= 1) v += __shfl_down_sync(0xffffffffu, v, o);
    if (d == 0) g_lpaff = -v;
}

__global__ void k_affine(const float* __restrict__ data,
                         const float* __restrict__ means,
                         const float* __restrict__ stds) {
    int i = blockIdx.x * blockDim.x + threadIdx.x;
    if (i < NS * DD) {
        int d = i & 31;
        g_z[i] = (data[i] - means[d]) / (10.0f * stds[d]);
    }
}

// ---------------- rational-linear spline inverse (scalar, matches pyro 'linear') -------
__device__ __forceinline__ float softplusf(float v) {
    return fmaxf(v, 0.0f) + log1pf(expf(-fabsf(v)));
}

__device__ __forceinline__ void rls_inv(
    float y,
    const float* __restrict__ wr, const float* __restrict__ hr,
    const float* __restrict__ dr, const float* __restrict__ lr,
    float& xo, float& lo_)
{
    const float BD = 3.0f;
    float w[BINSN], h[BINSN];
#pragma unroll
    for (int b = 0; b < BINSN; b++) { w[b] = wr[b]; h[b] = hr[b]; }

    bool inside = (y >= -BD) && (y <= BD);
    float yc = fminf(fmaxf(y, -BD), BD);

    // softmax(h); heights = MBH + (1 - MBH*B)*softmax
    float hm = h[0];
#pragma unroll
    for (int b = 1; b < BINSN; b++) hm = fmaxf(hm, h[b]);
    float hs = 0.f;
#pragma unroll
    for (int b = 0; b < BINSN; b++) { h[b] = expf(h[b] - hm); hs += h[b]; }
    float hscale = 0.984f / hs;   // (1 - 0.001*16)/sum

    // walk cumulative-height knots; locate bin: idx = last j with yc >= edge_j (clipped to 15)
    int idx = 0; float ich = -BD, ih = 0.f;
    {
        float prev = -BD, cs = 0.f;
#pragma unroll
        for (int b = 0; b < BINSN; b++) {
            float hb = 0.001f + hscale * h[b];
            cs += hb;
            float e = (b == BINSN - 1) ? BD : fmaf(6.0f, cs, -3.0f);
            if (yc >= prev) { idx = b; ich = prev; ih = e - prev; }
            prev = e;
        }
    }

    // softmax(w); pick width/left-knot of bin idx
    float wm = w[0];
#pragma unroll
    for (int b = 1; b < BINSN; b++) wm = fmaxf(wm, w[b]);
    float ws = 0.f;
#pragma unroll
    for (int b = 0; b < BINSN; b++) { w[b] = expf(w[b] - wm); ws += w[b]; }
    float wscale = 0.984f / ws;

    float icw = -BD, iw = 0.f;
    {
        float prev = -BD, cs = 0.f;
#pragma unroll
        for (int b = 0; b < BINSN; b++) {
            float wb_ = 0.001f + wscale * w[b];
            cs += wb_;
            float e = (b == BINSN - 1) ? BD : fmaf(6.0f, cs, -3.0f);
            if (b == idx) { icw = prev; iw = e - prev; }
            prev = e;
        }
    }

    // derivatives at bin edges (padded with 1-MD), lambda
    float idv   = (idx == 0)          ? 0.999f : (0.001f + softplusf(dr[idx - 1]));
    float idvp1 = (idx == BINSN - 1)  ? 0.999f : (0.001f + softplusf(dr[idx]));
    float il    = 0.025f + 0.95f / (1.0f + expf(-lr[idx]));

    float idel = ih / iw;
    float wb   = sqrtf(idv / idvp1);
    float wc   = (il * idv + (1.0f - il) * wb * idvp1) / idel;
    float ya = ich, yb = ih + ich;
    float ym = ((1.0f - il) * ya + il * wb * yb) / ((1.0f - il) + il * wb);

    bool left = (yc <= ym);
    float num, den, dnum;
    if (left) {
        num  = il * (ya - yc);
        den  = (wc - 1.0f) * yc + ya - wc * ym;
        dnum = wc * il * (ym - ya) * iw;
    } else {
        num  = (wc - il * wb) * yc + il * wb * yb - wc * ym;
        den  = (wc - wb) * yc + wb * yb - wc * ym;
        dnum = wb * wc * (1.0f - il) * (yb - ym) * iw;
    }
    float x  = num / den * iw + icw;
    float la = logf(dnum) - 2.0f * logf(fabsf(den));

    xo  = inside ? x  : y;
    lo_ = inside ? la : 0.0f;
}

// first-half spline: fixed per-dim params (broadcast over samples)
__global__ void k_spline1(const float* __restrict__ wp, const float* __restrict__ hp,
                          const float* __restrict__ dp, const float* __restrict__ lp,
                          int accumulate) {
    int i = blockIdx.x * blockDim.x + threadIdx.x;
    if (i >= NS * SPLITD) return;
    int n = i >> 4, j = i & 15;
    float y = g_z[n * DD + j];
    float x, la;
    rls_inv(y, wp + j * BINSN, hp + j * BINSN, dp + j * (BINSN - 1), lp + j * BINSN, x, la);
    g_z[n * DD + j] = x;
    if (accumulate) g_ladj[i] += la; else g_ladj[i] = la;
}

// second-half spline: per-sample params from MLP output row P[n, 1008]
__global__ void k_spline2() {
    int i = blockIdx.x * blockDim.x + threadIdx.x;
    if (i >= NS * D2) return;
    int n = i >> 4, j = i & 15;
    float y = g_z[n * DD + SPLITD + j];
    const float* pr = g_P + (size_t)n * POUT;
    float x, la;
    rls_inv(y,
            pr + j * BINSN,                 // w  raw
            pr + 256 + j * BINSN,           // h  raw
            pr + 512 + j * (BINSN - 1),     // d  raw
            pr + 752 + j * BINSN,           // l  raw
            x, la);
    g_z[n * DD + SPLITD + j] = x;
    g_ladj[i] += la;
}

// ---------------- SGEMM: C = act(A[M,K] * B[K,Nc] + bias), A has row stride lda ------
template <bool RELU>
__global__ void sgemm(const float* __restrict__ A, int lda,
                      const float* __restrict__ B,
                      const float* __restrict__ bias,
                      float* __restrict__ C,
                      int M, int Nc, int K) {
    __shared__ float As[16][65];      // +1 pad: kills 16-way store conflict
    __shared__ float Bs[16][64];

    const int t  = threadIdx.x;       // 256 threads
    const int tx = t & 15;            // N direction
    const int ty = t >> 4;            // M direction
    const int brow = blockIdx.y * 64;
    const int bcol = blockIdx.x * 64;

    float acc[4][4];
#pragma unroll
    for (int i = 0; i < 4; i++)
#pragma unroll
        for (int j = 0; j < 4; j++) acc[i][j] = 0.f;

    for (int k0 = 0; k0 < K; k0 += 16) {
        // A tile: 64 rows x 16 k  (M divisible by 64, K divisible by 16)
#pragma unroll
        for (int i = 0; i < 4; i++) {
            int idx = t + i * 256;
            int m = idx >> 4, kk = idx & 15;
            As[kk][m] = A[(size_t)(brow + m) * lda + k0 + kk];
        }
        // B tile: 16 k x 64 n (guard Nc)
#pragma unroll
        for (int i = 0; i < 4; i++) {
            int idx = t + i * 256;
            int kk = idx >> 6, n = idx & 63;
            int gn = bcol + n;
            Bs[kk][n] = (gn < Nc) ? B[(size_t)(k0 + kk) * Nc + gn] : 0.f;
        }
        __syncthreads();

#pragma unroll
        for (int kk = 0; kk < 16; kk++) {
            float a[4], b[4];
#pragma unroll
            for (int i = 0; i < 4; i++) a[i] = As[kk][ty * 4 + i];
#pragma unroll
            for (int j = 0; j < 4; j++) b[j] = Bs[kk][tx * 4 + j];
#pragma unroll
            for (int i = 0; i < 4; i++)
#pragma unroll
                for (int j = 0; j < 4; j++)
                    acc[i][j] = fmaf(a[i], b[j], acc[i][j]);
        }
        __syncthreads();
    }

#pragma unroll
    for (int i = 0; i < 4; i++) {
        int gm = brow + ty * 4 + i;
#pragma unroll
        for (int j = 0; j < 4; j++) {
            int gn = bcol + tx * 4 + j;
            if (gn < Nc) {
                float v = acc[i][j] + bias[gn];
                if (RELU) v = fmaxf(v, 0.f);
                C[(size_t)gm * Nc + gn] = v;
            }
        }
    }
}

// ---------------- epilogue ----------------
__global__ void k_final(float* __restrict__ out) {
    int n = blockIdx.x * blockDim.x + threadIdx.x;
    if (n >= NS) return;
    float ss = 0.f;
#pragma unroll
    for (int d = 0; d < DD; d++) { float z = g_z[n * DD + d]; ss = fmaf(z, z, ss); }
    float ls = 0.f;
#pragma unroll
    for (int j = 0; j < SPLITD; j++) ls += g_ladj[n * SPLITD + j];
    out[n] = -0.5f * ss - 0.5f * (float)DD * LOG2PI_F + ls + g_lpaff;
}

// ---------------- launch ----------------
extern "C" void kernel_launch(void* const* d_in, const int* in_sizes, int n_in,
                              void* d_out, int out_size) {
    const float* data  = (const float*)d_in[0];
    const float* means = (const float*)d_in[1];
    const float* stds  = (const float*)d_in[2];

    const float* t1w  = (const float*)d_in[3];
    const float* t1h  = (const float*)d_in[4];
    const float* t1d  = (const float*)d_in[5];
    const float* t1l  = (const float*)d_in[6];
    const float* t1W1 = (const float*)d_in[7];
    const float* t1b1 = (const float*)d_in[8];
    const float* t1W2 = (const float*)d_in[9];
    const float* t1b2 = (const float*)d_in[10];
    const float* t1W3 = (const float*)d_in[11];
    const float* t1b3 = (const float*)d_in[12];

    const float* t2w  = (const float*)d_in[13];
    const float* t2h  = (const float*)d_in[14];
    const float* t2d  = (const float*)d_in[15];
    const float* t2l  = (const float*)d_in[16];
    const float* t2W1 = (const float*)d_in[17];
    const float* t2b1 = (const float*)d_in[18];
    const float* t2W2 = (const float*)d_in[19];
    const float* t2b2 = (const float*)d_in[20];
    const float* t2W3 = (const float*)d_in[21];
    const float* t2b3 = (const float*)d_in[22];

    float* out = (float*)d_out;

    float *pz, *pH1, *pH2, *pP;
    cudaGetSymbolAddress((void**)&pz,  g_z);
    cudaGetSymbolAddress((void**)&pH1, g_H1);
    cudaGetSymbolAddress((void**)&pH2, g_H2);
    cudaGetSymbolAddress((void**)&pP,  g_P);

    k_lpaff<<<1, 32>>>(stds);
    k_affine<<<(NS * DD) / 256, 256>>>(data, means, stds);

    const int splineBlocks = (NS * SPLITD) / 256;
    dim3 blk(256);
    dim3 gH((HID  + 63) / 64, NS / 64);
    dim3 gP((POUT + 63) / 64, NS / 64);

    // ---- layer t2 (applied first) ----
    k_spline1<<<splineBlocks, 256>>>(t2w, t2h, t2d, t2l, /*accumulate=*/0);
    sgemm<true ><<<gH, blk>>>(pz,  DD,  t2W1, t2b1, pH1, NS, HID,  SPLITD);
    sgemm<true ><<<gH, blk>>>(pH1, HID, t2W2, t2b2, pH2, NS, HID,  HID);
    sgemm<false><<<gP, blk>>>(pH2, HID, t2W3, t2b3, pP,  NS, POUT, HID);
    k_spline2<<<splineBlocks, 256>>>();

    // ---- layer t1 ----
    k_spline1<<<splineBlocks, 256>>>(t1w, t1h, t1d, t1l, /*accumulate=*/1);
    sgemm<true ><<<gH, blk>>>(pz,  DD,  t1W1, t1b1, pH1, NS, HID,  SPLITD);
    sgemm<true ><<<gH, blk>>>(pH1, HID, t1W2, t1b2, pH2, NS, HID,  HID);
    sgemm<false><<<gP, blk>>>(pH2, HID, t1W3, t1b3, pP,  NS, POUT, HID);
    k_spline2<<<splineBlocks, 256>>>();

    k_final<<<NS / 256, 256>>>(out);
}

// round 3
// speedup vs baseline: 2.5117x; 2.5117x over previous
#include <cuda_runtime.h>
#include <cuda_bf16.h>
#include <math.h>
#include <stdint.h>

#define NS    32768
#define DD    32
#define SPLITD 16
#define D2    16
#define BINSN 16
#define HID   320
#define POUT  1008
#define LOG2PI_F 1.8378770664093453f

// padded GEMM dims
#define KP1   32      // GEMM1 K padded (real 16)
#define NP12  384     // GEMM1/2 N padded (real 320)
#define NP3   1024    // GEMM3 N padded (real 1008)

// ================= scratch (device globals; zero-initialized at load) =================
__device__ float g_z[NS * DD];
__device__ float g_ladj[NS * SPLITD];
__device__ float g_lpaff;
__device__ float g_P[(size_t)NS * POUT];

__device__ __nv_bfloat16 g_x1h[NS * KP1];   // pad cols stay zero forever
__device__ __nv_bfloat16 g_x1l[NS * KP1];
__device__ __nv_bfloat16 g_H1h[NS * HID];
__device__ __nv_bfloat16 g_H1l[NS * HID];
__device__ __nv_bfloat16 g_H2h[NS * HID];
__device__ __nv_bfloat16 g_H2l[NS * HID];

__device__ __nv_bfloat16 g_W1th[NP12 * KP1];
__device__ __nv_bfloat16 g_W1tl[NP12 * KP1];
__device__ __nv_bfloat16 g_W2th[NP12 * HID];
__device__ __nv_bfloat16 g_W2tl[NP12 * HID];
__device__ __nv_bfloat16 g_W3th[(size_t)NP3 * HID];
__device__ __nv_bfloat16 g_W3tl[(size_t)NP3 * HID];

// ================= helpers =================
__device__ __forceinline__ uint32_t smem_u32(const void* p) {
    uint32_t a;
    asm("{ .reg .u64 t; cvta.to.shared.u64 t, %1; cvt.u32.u64 %0, t; }" : "=r"(a) : "l"(p));
    return a;
}
__device__ __forceinline__ void cp16(uint32_t dst, const void* src) {
    asm volatile("cp.async.cg.shared.global [%0], [%1], 16;" :: "r"(dst), "l"(src));
}
__device__ __forceinline__ void ldsm4(uint32_t& r0, uint32_t& r1, uint32_t& r2, uint32_t& r3, uint32_t a) {
    asm volatile("ldmatrix.sync.aligned.m8n8.x4.shared.b16 {%0,%1,%2,%3}, [%4];"
                 : "=r"(r0), "=r"(r1), "=r"(r2), "=r"(r3) : "r"(a));
}
__device__ __forceinline__ void mma_bf16(float* c, const uint32_t* a, const uint32_t* b) {
    asm volatile("mma.sync.aligned.m16n8k16.row.col.f32.bf16.bf16.f32 "
                 "{%0,%1,%2,%3}, {%4,%5,%6,%7}, {%8,%9}, {%0,%1,%2,%3};"
                 : "+f"(c[0]), "+f"(c[1]), "+f"(c[2]), "+f"(c[3])
                 : "r"(a[0]), "r"(a[1]), "r"(a[2]), "r"(a[3]), "r"(b[0]), "r"(b[1]));
}

// ================= small kernels =================
__global__ void k_lpaff(const float* __restrict__ stds) {
    int d = threadIdx.x;
    float v = logf(10.0f * stds[d]);
#pragma unroll
    for (int o = 16; o > 0; o >>= 1) v += __shfl_down_sync(0xffffffffu, v, o);
    if (d == 0) g_lpaff = -v;
}

__global__ void k_affine(const float* __restrict__ data,
                         const float* __restrict__ means,
                         const float* __restrict__ stds) {
    int i = blockIdx.x * blockDim.x + threadIdx.x;
    if (i < NS * DD) {
        int d = i & 31;
        g_z[i] = (data[i] - means[d]) / (10.0f * stds[d]);
    }
}

// weight prep: W [K,N] fp32 -> Wt_hi/lo [Np,Kp] bf16, transposed + zero-padded
__global__ void k_prepw(const float* __restrict__ W,
                        __nv_bfloat16* __restrict__ Th, __nv_bfloat16* __restrict__ Tl,
                        int K, int N, int Kp, int Np) {
    int idx = blockIdx.x * blockDim.x + threadIdx.x;
    if (idx >= Np * Kp) return;
    int n = idx / Kp, k = idx % Kp;
    float v = (n < N && k < K) ? W[(size_t)k * N + n] : 0.0f;
    __nv_bfloat16 hi = __float2bfloat16(v);
    Th[idx] = hi;
    Tl[idx] = __float2bfloat16(v - __bfloat162float(hi));
}

// ================= spline inverse =================
__device__ __forceinline__ float softplusf(float v) {
    return fmaxf(v, 0.0f) + log1pf(expf(-fabsf(v)));
}

__device__ __forceinline__ void rls_inv(
    float y,
    const float* __restrict__ wr, const float* __restrict__ hr,
    const float* __restrict__ dr, const float* __restrict__ lr,
    float& xo, float& lo_)
{
    const float BD = 3.0f;
    float w[BINSN], h[BINSN];
#pragma unroll
    for (int b = 0; b < BINSN; b++) { w[b] = wr[b]; h[b] = hr[b]; }

    bool inside = (y >= -BD) && (y <= BD);
    float yc = fminf(fmaxf(y, -BD), BD);

    float hm = h[0];
#pragma unroll
    for (int b = 1; b < BINSN; b++) hm = fmaxf(hm, h[b]);
    float hs = 0.f;
#pragma unroll
    for (int b = 0; b < BINSN; b++) { h[b] = expf(h[b] - hm); hs += h[b]; }
    float hscale = 0.984f / hs;

    int idx = 0; float ich = -BD, ih = 0.f;
    {
        float prev = -BD, cs = 0.f;
#pragma unroll
        for (int b = 0; b < BINSN; b++) {
            float hb = 0.001f + hscale * h[b];
            cs += hb;
            float e = (b == BINSN - 1) ? BD : fmaf(6.0f, cs, -3.0f);
            if (yc >= prev) { idx = b; ich = prev; ih = e - prev; }
            prev = e;
        }
    }

    float wm = w[0];
#pragma unroll
    for (int b = 1; b < BINSN; b++) wm = fmaxf(wm, w[b]);
    float ws = 0.f;
#pragma unroll
    for (int b = 0; b < BINSN; b++) { w[b] = expf(w[b] - wm); ws += w[b]; }
    float wscale = 0.984f / ws;

    float icw = -BD, iw = 0.f;
    {
        float prev = -BD, cs = 0.f;
#pragma unroll
        for (int b = 0; b < BINSN; b++) {
            float wb_ = 0.001f + wscale * w[b];
            cs += wb_;
            float e = (b == BINSN - 1) ? BD : fmaf(6.0f, cs, -3.0f);
            if (b == idx) { icw = prev; iw = e - prev; }
            prev = e;
        }
    }

    float idv   = (idx == 0)         ? 0.999f : (0.001f + softplusf(dr[idx - 1]));
    float idvp1 = (idx == BINSN - 1) ? 0.999f : (0.001f + softplusf(dr[idx]));
    float il    = 0.025f + 0.95f / (1.0f + expf(-lr[idx]));

    float idel = ih / iw;
    float wb   = sqrtf(idv / idvp1);
    float wc   = (il * idv + (1.0f - il) * wb * idvp1) / idel;
    float ya = ich, yb = ih + ich;
    float ym = ((1.0f - il) * ya + il * wb * yb) / ((1.0f - il) + il * wb);

    bool left = (yc <= ym);
    float num, den, dnum;
    if (left) {
        num  = il * (ya - yc);
        den  = (wc - 1.0f) * yc + ya - wc * ym;
        dnum = wc * il * (ym - ya) * iw;
    } else {
        num  = (wc - il * wb) * yc + il * wb * yb - wc * ym;
        den  = (wc - wb) * yc + wb * yb - wc * ym;
        dnum = wb * wc * (1.0f - il) * (yb - ym) * iw;
    }
    float x  = num / den * iw + icw;
    float la = logf(dnum) - 2.0f * logf(fabsf(den));

    xo  = inside ? x  : y;
    lo_ = inside ? la : 0.0f;
}

__global__ void k_spline1(const float* __restrict__ wp, const float* __restrict__ hp,
                          const float* __restrict__ dp, const float* __restrict__ lp,
                          int accumulate) {
    int i = blockIdx.x * blockDim.x + threadIdx.x;
    if (i >= NS * SPLITD) return;
    int n = i >> 4, j = i & 15;
    float y = g_z[n * DD + j];
    float x, la;
    rls_inv(y, wp + j * BINSN, hp + j * BINSN, dp + j * (BINSN - 1), lp + j * BINSN, x, la);
    g_z[n * DD + j] = x;
    __nv_bfloat16 hi = __float2bfloat16(x);
    g_x1h[n * KP1 + j] = hi;
    g_x1l[n * KP1 + j] = __float2bfloat16(x - __bfloat162float(hi));
    if (accumulate) g_ladj[i] += la; else g_ladj[i] = la;
}

__global__ void k_spline2() {
    int i = blockIdx.x * blockDim.x + threadIdx.x;
    if (i >= NS * D2) return;
    int n = i >> 4, j = i & 15;
    float y = g_z[n * DD + SPLITD + j];
    const float* pr = g_P + (size_t)n * POUT;
    float x, la;
    rls_inv(y,
            pr + j * BINSN,
            pr + 256 + j * BINSN,
            pr + 512 + j * (BINSN - 1),
            pr + 752 + j * BINSN,
            x, la);
    g_z[n * DD + SPLITD + j] = x;
    g_ladj[i] += la;
}

// ================= HMMA split-bf16 GEMM =================
// C[128x128 tile] = A[M,K] * B^T, B stored [Npad,K] K-major.
// 3-product emulation: Ah*Bh + Ah*Bl + Al*Bh, fp32 accumulators.
// smem tile: 128 rows x 32 bf16, row stride 80B (conflict-free ldmatrix).
#define RSTR   80                       // bytes per smem row
#define TBYTES (128 * RSTR)             // 10240 per matrix
#define SM_AH(s) ((s) * 4 * TBYTES + 0 * TBYTES)
#define SM_AL(s) ((s) * 4 * TBYTES + 1 * TBYTES)
#define SM_BH(s) ((s) * 4 * TBYTES + 2 * TBYTES)
#define SM_BL(s) ((s) * 4 * TBYTES + 3 * TBYTES)
#define SM_TOTAL (2 * 4 * TBYTES)       // 81920

template <bool RELU, bool F32OUT>
__global__ void __launch_bounds__(256) hgemm(
    const __nv_bfloat16* __restrict__ Ah, const __nv_bfloat16* __restrict__ Al,
    const __nv_bfloat16* __restrict__ Bh, const __nv_bfloat16* __restrict__ Bl,
    const float* __restrict__ bias,
    int K, int Nreal, int ldc,
    __nv_bfloat16* __restrict__ Ch, __nv_bfloat16* __restrict__ Cl,
    float* __restrict__ Cf)
{
    extern __shared__ char smem[];
    const uint32_t sb = smem_u32(smem);
    const int tid = threadIdx.x;
    const int wid = tid >> 5, lane = tid & 31;
    const int wm = wid >> 1, wn = wid & 1;          // 4 x 2 warp grid

    const int brow = blockIdx.y * 128;
    const int bcol = blockIdx.x * 128;
    const int nch = K >> 5;

    float acc[2][8][4];
#pragma unroll
    for (int i = 0; i < 2; i++)
#pragma unroll
        for (int j = 0; j < 8; j++)
#pragma unroll
            for (int q = 0; q < 4; q++) acc[i][j][q] = 0.f;

    // ---- tile loader: 512 cp16 units per chunk (2 passes x 256 threads) ----
    auto load_chunk = [&](int ch, int stage) {
        const int k0 = ch * 32;
#pragma unroll
        for (int p = 0; p < 2; p++) {
            int idx = tid + p * 256;            // 0..511
            int r = idx >> 2, c = idx & 3;      // row 0..127, 16B col 0..3
            uint32_t so = (uint32_t)(r * RSTR + c * 16);
            size_t aoff = (size_t)(brow + r) * K + k0 + c * 8;
            size_t boff = (size_t)(bcol + r) * K + k0 + c * 8;
            cp16(sb + SM_AH(stage) + so, Ah + aoff);
            cp16(sb + SM_AL(stage) + so, Al + aoff);
            cp16(sb + SM_BH(stage) + so, Bh + boff);
            cp16(sb + SM_BL(stage) + so, Bl + boff);
        }
        asm volatile("cp.async.commit_group;" ::: "memory");
    };

    load_chunk(0, 0);

    for (int ch = 0; ch < nch; ch++) {
        if (ch + 1 < nch) {
            load_chunk(ch + 1, (ch + 1) & 1);
            asm volatile("cp.async.wait_group 1;" ::: "memory");
        } else {
            asm volatile("cp.async.wait_group 0;" ::: "memory");
        }
        __syncthreads();

        const int st = ch & 1;
        const uint32_t abase = sb + SM_AH(st), albase = sb + SM_AL(st);
        const uint32_t bbase = sb + SM_BH(st), blbase = sb + SM_BL(st);

#pragma unroll
        for (int ks = 0; ks < 2; ks++) {
            // A fragments: 2 m16 tiles, hi+lo
            uint32_t a_h[2][4], a_l[2][4];
            const uint32_t arow = (uint32_t)(wm * 32 + (lane & 15));
            const uint32_t akb  = (uint32_t)(ks * 32 + ((lane >> 4) & 1) * 16);
#pragma unroll
            for (int tm = 0; tm < 2; tm++) {
                uint32_t off = (arow + tm * 16) * RSTR + akb;
                ldsm4(a_h[tm][0], a_h[tm][1], a_h[tm][2], a_h[tm][3], abase + off);
                ldsm4(a_l[tm][0], a_l[tm][1], a_l[tm][2], a_l[tm][3], albase + off);
            }
            // B fragments: 8 n8 tiles, loaded pairwise via x4
            uint32_t b_h[8][2], b_l[8][2];
            const uint32_t nrow0 = (uint32_t)(wn * 64 + (lane & 7) + ((lane >> 4) & 1) * 8);
            const uint32_t bkb   = (uint32_t)(ks * 32 + ((lane >> 3) & 1) * 16);
#pragma unroll
            for (int tp = 0; tp < 4; tp++) {
                uint32_t off = (nrow0 + tp * 16) * RSTR + bkb;
                ldsm4(b_h[tp * 2][0], b_h[tp * 2][1], b_h[tp * 2 + 1][0], b_h[tp * 2 + 1][1], bbase + off);
                ldsm4(b_l[tp * 2][0], b_l[tp * 2][1], b_l[tp * 2 + 1][0], b_l[tp * 2 + 1][1], blbase + off);
            }
#pragma unroll
            for (int tm = 0; tm < 2; tm++)
#pragma unroll
                for (int tn = 0; tn < 8; tn++) {
                    mma_bf16(acc[tm][tn], a_h[tm], b_h[tn]);
                    mma_bf16(acc[tm][tn], a_h[tm], b_l[tn]);
                    mma_bf16(acc[tm][tn], a_l[tm], b_h[tn]);
                }
        }
        __syncthreads();
    }

    // ---- epilogue: bias (+ReLU), write bf16 hi/lo pair or fp32 ----
#pragma unroll
    for (int tm = 0; tm < 2; tm++) {
#pragma unroll
        for (int tn = 0; tn < 8; tn++) {
            int n = bcol + wn * 64 + tn * 8 + 2 * (lane & 3);
            if (n >= Nreal) continue;
            float bb0 = bias[n], bb1 = bias[n + 1];
#pragma unroll
            for (int half = 0; half < 2; half++) {
                int m = brow + wm * 32 + tm * 16 + (lane >> 2) + half * 8;
                float v0 = acc[tm][tn][half * 2 + 0] + bb0;
                float v1 = acc[tm][tn][half * 2 + 1] + bb1;
                if (RELU) { v0 = fmaxf(v0, 0.f); v1 = fmaxf(v1, 0.f); }
                if (F32OUT) {
                    *reinterpret_cast<float2*>(Cf + (size_t)m * ldc + n) = make_float2(v0, v1);
                } else {
                    __nv_bfloat16 h0 = __float2bfloat16(v0);
                    __nv_bfloat16 h1 = __float2bfloat16(v1);
                    __nv_bfloat16 l0 = __float2bfloat16(v0 - __bfloat162float(h0));
                    __nv_bfloat16 l1 = __float2bfloat16(v1 - __bfloat162float(h1));
                    uint32_t hp = (uint32_t)__bfloat16_as_ushort(h0) | ((uint32_t)__bfloat16_as_ushort(h1) << 16);
                    uint32_t lp = (uint32_t)__bfloat16_as_ushort(l0) | ((uint32_t)__bfloat16_as_ushort(l1) << 16);
                    *reinterpret_cast<uint32_t*>(Ch + (size_t)m * ldc + n) = hp;
                    *reinterpret_cast<uint32_t*>(Cl + (size_t)m * ldc + n) = lp;
                }
            }
        }
    }
}

// ================= epilogue =================
__global__ void k_final(float* __restrict__ out) {
    int n = blockIdx.x * blockDim.x + threadIdx.x;
    if (n >= NS) return;
    float ss = 0.f;
#pragma unroll
    for (int d = 0; d < DD; d++) { float z = g_z[n * DD + d]; ss = fmaf(z, z, ss); }
    float ls = 0.f;
#pragma unroll
    for (int j = 0; j < SPLITD; j++) ls += g_ladj[n * SPLITD + j];
    out[n] = -0.5f * ss - 0.5f * (float)DD * LOG2PI_F + ls + g_lpaff;
}

// ================= launch =================
extern "C" void kernel_launch(void* const* d_in, const int* in_sizes, int n_in,
                              void* d_out, int out_size) {
    const float* data  = (const float*)d_in[0];
    const float* means = (const float*)d_in[1];
    const float* stds  = (const float*)d_in[2];

    const float* tw[2]  = { (const float*)d_in[13], (const float*)d_in[3] };
    const float* th[2]  = { (const float*)d_in[14], (const float*)d_in[4] };
    const float* td[2]  = { (const float*)d_in[15], (const float*)d_in[5] };
    const float* tl[2]  = { (const float*)d_in[16], (const float*)d_in[6] };
    const float* tW1[2] = { (const float*)d_in[17], (const float*)d_in[7] };
    const float* tb1[2] = { (const float*)d_in[18], (const float*)d_in[8] };
    const float* tW2[2] = { (const float*)d_in[19], (const float*)d_in[9] };
    const float* tb2[2] = { (const float*)d_in[20], (const float*)d_in[10] };
    const float* tW3[2] = { (const float*)d_in[21], (const float*)d_in[11] };
    const float* tb3[2] = { (const float*)d_in[22], (const float*)d_in[12] };

    float* out = (float*)d_out;

    __nv_bfloat16 *x1h, *x1l, *H1h, *H1l, *H2h, *H2l;
    __nv_bfloat16 *W1th, *W1tl, *W2th, *W2tl, *W3th, *W3tl;
    float* pP;
    cudaGetSymbolAddress((void**)&x1h, g_x1h);  cudaGetSymbolAddress((void**)&x1l, g_x1l);
    cudaGetSymbolAddress((void**)&H1h, g_H1h);  cudaGetSymbolAddress((void**)&H1l, g_H1l);
    cudaGetSymbolAddress((void**)&H2h, g_H2h);  cudaGetSymbolAddress((void**)&H2l, g_H2l);
    cudaGetSymbolAddress((void**)&W1th, g_W1th); cudaGetSymbolAddress((void**)&W1tl, g_W1tl);
    cudaGetSymbolAddress((void**)&W2th, g_W2th); cudaGetSymbolAddress((void**)&W2tl, g_W2tl);
    cudaGetSymbolAddress((void**)&W3th, g_W3th); cudaGetSymbolAddress((void**)&W3tl, g_W3tl);
    cudaGetSymbolAddress((void**)&pP, g_P);

    cudaFuncSetAttribute(hgemm<true,  false>, cudaFuncAttributeMaxDynamicSharedMemorySize, SM_TOTAL);
    cudaFuncSetAttribute(hgemm<false, true >, cudaFuncAttributeMaxDynamicSharedMemorySize, SM_TOTAL);

    k_lpaff<<<1, 32>>>(stds);
    k_affine<<<(NS * DD) / 256, 256>>>(data, means, stds);

    const int splineBlocks = (NS * SPLITD) / 256;
    dim3 g12(NP12 / 128, NS / 128);  // (3, 256)
    dim3 g3 (NP3  / 128, NS / 128);  // (8, 256)

    for (int L = 0; L < 2; L++) {   // L=0 -> t2 (applied first), L=1 -> t1
        k_prepw<<<(NP12 * KP1 + 255) / 256, 256>>>(tW1[L], W1th, W1tl, SPLITD, HID, KP1, NP12);
        k_prepw<<<(NP12 * HID + 255) / 256, 256>>>(tW2[L], W2th, W2tl, HID, HID, HID, NP12);
        k_prepw<<<(NP3  * HID + 255) / 256, 256>>>(tW3[L], W3th, W3tl, HID, POUT, HID, NP3);

        k_spline1<<<splineBlocks, 256>>>(tw[L], th[L], td[L], tl[L], /*accumulate=*/L);

        hgemm<true,  false><<<g12, 256, SM_TOTAL>>>(x1h, x1l, W1th, W1tl, tb1[L],
                                                    KP1, HID, HID, H1h, H1l, nullptr);
        hgemm<true,  false><<<g12, 256, SM_TOTAL>>>(H1h, H1l, W2th, W2tl, tb2[L],
                                                    HID, HID, HID, H2h, H2l, nullptr);
        hgemm<false, true ><<<g3,  256, SM_TOTAL>>>(H2h, H2l, W3th, W3tl, tb3[L],
                                                    HID, POUT, POUT, nullptr, nullptr, pP);

        k_spline2<<<splineBlocks, 256>>>();
    }

    k_final<<<NS / 256, 256>>>(out);
}

// round 4
// speedup vs baseline: 3.5918x; 1.4300x over previous
#include <cuda_runtime.h>
#include <cuda_fp16.h>
#include <math.h>
#include <stdint.h>

#define NS    32768
#define DD    32
#define SPLITD 16
#define BINSN 16
#define HID   320
#define POUT  1008
#define LOG2PI_F 1.8378770664093453f

// padded GEMM dims
#define KP1   64      // GEMM1 K padded (real 16)
#define NP12  384     // GEMM1/2 N padded (real 320)
#define NP3   1024    // GEMM3 N padded (real 1008)

// ================= scratch (device globals; zero-initialized at load) =================
__device__ float g_z[NS * DD];
__device__ float g_ladj[NS * SPLITD];
__device__ float g_P[(size_t)NS * POUT];

__device__ __half g_x1[NS * KP1];     // pad cols stay zero forever
__device__ __half g_H1[NS * HID];
__device__ __half g_H2[NS * HID];

__device__ __half g_W1th[NP12 * KP1];
__device__ __half g_W1tl[NP12 * KP1];
__device__ __half g_W2th[NP12 * HID];
__device__ __half g_W2tl[NP12 * HID];
__device__ __half g_W3th[(size_t)NP3 * HID];
__device__ __half g_W3tl[(size_t)NP3 * HID];

// ================= helpers =================
__device__ __forceinline__ uint32_t smem_u32(const void* p) {
    uint32_t a;
    asm("{ .reg .u64 t; cvta.to.shared.u64 t, %1; cvt.u32.u64 %0, t; }" : "=r"(a) : "l"(p));
    return a;
}
__device__ __forceinline__ void cp16(uint32_t dst, const void* src) {
    asm volatile("cp.async.cg.shared.global [%0], [%1], 16;" :: "r"(dst), "l"(src));
}
__device__ __forceinline__ void ldsm4(uint32_t& r0, uint32_t& r1, uint32_t& r2, uint32_t& r3, uint32_t a) {
    asm volatile("ldmatrix.sync.aligned.m8n8.x4.shared.b16 {%0,%1,%2,%3}, [%4];"
                 : "=r"(r0), "=r"(r1), "=r"(r2), "=r"(r3) : "r"(a));
}
__device__ __forceinline__ void mma_f16(float* c, const uint32_t* a, const uint32_t* b) {
    asm volatile("mma.sync.aligned.m16n8k16.row.col.f32.f16.f16.f32 "
                 "{%0,%1,%2,%3}, {%4,%5,%6,%7}, {%8,%9}, {%0,%1,%2,%3};"
                 : "+f"(c[0]), "+f"(c[1]), "+f"(c[2]), "+f"(c[3])
                 : "r"(a[0]), "r"(a[1]), "r"(a[2]), "r"(a[3]), "r"(b[0]), "r"(b[1]));
}

// ================= weight prep: all three weights of a layer in one launch ==========
// W [K,N] fp32 -> Wt_hi/lo [Np,Kp] fp16, transposed + zero-padded.
#define SEG1 (NP12 * KP1)            // 24576
#define SEG2 (NP12 * HID)            // 122880
#define SEG3 (NP3 * HID)             // 327680
#define PREP_TOT (SEG1 + SEG2 + SEG3)

__global__ void k_prepall(const float* __restrict__ W1, const float* __restrict__ W2,
                          const float* __restrict__ W3) {
    int idx = blockIdx.x * blockDim.x + threadIdx.x;
    const float* W; __half *Th, *Tl; int K, N, Kp;
    if (idx < SEG1)              { W = W1; Th = g_W1th; Tl = g_W1tl; K = SPLITD; N = HID;  Kp = KP1; }
    else if (idx < SEG1 + SEG2)  { idx -= SEG1; W = W2; Th = g_W2th; Tl = g_W2tl; K = HID; N = HID;  Kp = HID; }
    else if (idx < PREP_TOT)     { idx -= SEG1 + SEG2; W = W3; Th = g_W3th; Tl = g_W3tl; K = HID; N = POUT; Kp = HID; }
    else return;
    int n = idx / Kp, k = idx - n * Kp;
    float v = (n < N && k < K) ? W[(size_t)k * N + n] : 0.0f;
    __half hi = __float2half_rn(v);
    Th[idx] = hi;
    Tl[idx] = __float2half_rn(v - __half2float(hi));
}

// ================= spline inverse =================
__device__ __forceinline__ float softplusf(float v) {
    return fmaxf(v, 0.0f) + log1pf(expf(-fabsf(v)));
}

__device__ __forceinline__ void rls_inv(
    float y,
    const float* __restrict__ wr, const float* __restrict__ hr,
    const float* __restrict__ dr, const float* __restrict__ lr,
    float& xo, float& lo_)
{
    const float BD = 3.0f;
    float w[BINSN], h[BINSN];
#pragma unroll
    for (int b = 0; b < BINSN; b++) { w[b] = wr[b]; h[b] = hr[b]; }

    bool inside = (y >= -BD) && (y <= BD);
    float yc = fminf(fmaxf(y, -BD), BD);

    float hm = h[0];
#pragma unroll
    for (int b = 1; b < BINSN; b++) hm = fmaxf(hm, h[b]);
    float hs = 0.f;
#pragma unroll
    for (int b = 0; b < BINSN; b++) { h[b] = expf(h[b] - hm); hs += h[b]; }
    float hscale = 0.984f / hs;

    int idx = 0; float ich = -BD, ih = 0.f;
    {
        float prev = -BD, cs = 0.f;
#pragma unroll
        for (int b = 0; b < BINSN; b++) {
            float hb = 0.001f + hscale * h[b];
            cs += hb;
            float e = (b == BINSN - 1) ? BD : fmaf(6.0f, cs, -3.0f);
            if (yc >= prev) { idx = b; ich = prev; ih = e - prev; }
            prev = e;
        }
    }

    float wm = w[0];
#pragma unroll
    for (int b = 1; b < BINSN; b++) wm = fmaxf(wm, w[b]);
    float ws = 0.f;
#pragma unroll
    for (int b = 0; b < BINSN; b++) { w[b] = expf(w[b] - wm); ws += w[b]; }
    float wscale = 0.984f / ws;

    float icw = -BD, iw = 0.f;
    {
        float prev = -BD, cs = 0.f;
#pragma unroll
        for (int b = 0; b < BINSN; b++) {
            float wb_ = 0.001f + wscale * w[b];
            cs += wb_;
            float e = (b == BINSN - 1) ? BD : fmaf(6.0f, cs, -3.0f);
            if (b == idx) { icw = prev; iw = e - prev; }
            prev = e;
        }
    }

    float idv   = (idx == 0)         ? 0.999f : (0.001f + softplusf(dr[idx - 1]));
    float idvp1 = (idx == BINSN - 1) ? 0.999f : (0.001f + softplusf(dr[idx]));
    float il    = 0.025f + 0.95f / (1.0f + expf(-lr[idx]));

    float idel = ih / iw;
    float wb   = sqrtf(idv / idvp1);
    float wc   = (il * idv + (1.0f - il) * wb * idvp1) / idel;
    float ya = ich, yb = ih + ich;
    float ym = ((1.0f - il) * ya + il * wb * yb) / ((1.0f - il) + il * wb);

    bool left = (yc <= ym);
    float num, den, dnum;
    if (left) {
        num  = il * (ya - yc);
        den  = (wc - 1.0f) * yc + ya - wc * ym;
        dnum = wc * il * (ym - ya) * iw;
    } else {
        num  = (wc - il * wb) * yc + il * wb * yb - wc * ym;
        den  = (wc - wb) * yc + wb * yb - wc * ym;
        dnum = wb * wc * (1.0f - il) * (yb - ym) * iw;
    }
    float x  = num / den * iw + icw;
    float la = logf(dnum) - 2.0f * logf(fabsf(den));

    xo  = inside ? x  : y;
    lo_ = inside ? la : 0.0f;
}

// spline1 over first half; FIRST variant also applies the affine prelude to both halves
template <bool FIRST>
__global__ void k_spline1(const float* __restrict__ data,
                          const float* __restrict__ means,
                          const float* __restrict__ stds,
                          const float* __restrict__ wp, const float* __restrict__ hp,
                          const float* __restrict__ dp, const float* __restrict__ lp) {
    int i = blockIdx.x * blockDim.x + threadIdx.x;
    if (i >= NS * SPLITD) return;
    int n = i >> 4, j = i & 15;
    float y;
    if (FIRST) {
        y = (data[n * DD + j] - means[j]) / (10.0f * stds[j]);
        float y2 = (data[n * DD + j + 16] - means[j + 16]) / (10.0f * stds[j + 16]);
        g_z[n * DD + j + 16] = y2;
    } else {
        y = g_z[n * DD + j];
    }
    float x, la;
    rls_inv(y, wp + j * BINSN, hp + j * BINSN, dp + j * (BINSN - 1), lp + j * BINSN, x, la);
    g_z[n * DD + j] = x;
    g_x1[n * KP1 + j] = __float2half_rn(x);
    if (FIRST) g_ladj[i] = la; else g_ladj[i] += la;
}

__global__ void k_spline2() {
    int i = blockIdx.x * blockDim.x + threadIdx.x;
    if (i >= NS * SPLITD) return;
    int n = i >> 4, j = i & 15;
    float y = g_z[n * DD + SPLITD + j];
    const float* pr = g_P + (size_t)n * POUT;
    float x, la;
    rls_inv(y,
            pr + j * BINSN,
            pr + 256 + j * BINSN,
            pr + 512 + j * (BINSN - 1),
            pr + 752 + j * BINSN,
            x, la);
    g_z[n * DD + SPLITD + j] = x;
    g_ladj[i] += la;
}

// ================= HMMA fp16 weight-split GEMM =================
// C[128x128 tile] = A[M,K] * B^T, B stored [Npad,K] K-major, B split hi+lo fp16.
// 2-product: A*(Bh) + A*(Bl).  fp32 accumulators.
// smem: 128 rows x 64 fp16, row stride 144B (conflict-free ldmatrix). BK=64.
#define RSTR    144
#define TILE_B  (128 * RSTR)          // 18432
#define STAGE_B (3 * TILE_B)          // 55296
#define SM_TOTAL (2 * STAGE_B)        // 110592

template <bool RELU, bool F32OUT>
__global__ void __launch_bounds__(256, 2) hgemm(
    const __half* __restrict__ A,
    const __half* __restrict__ Bh, const __half* __restrict__ Bl,
    const float* __restrict__ bias,
    int K, int Nreal, int ldc,
    __half* __restrict__ Ch, float* __restrict__ Cf)
{
    extern __shared__ char smem[];
    const uint32_t sb = smem_u32(smem);
    const int tid = threadIdx.x;
    const int wid = tid >> 5, lane = tid & 31;
    const int wm = wid >> 1, wn = wid & 1;          // 4 x 2 warp grid, warp tile 32x64

    const int brow = blockIdx.y * 128;
    const int bcol = blockIdx.x * 128;
    const int nch = K >> 6;

    float acc[2][8][4];
#pragma unroll
    for (int i = 0; i < 2; i++)
#pragma unroll
        for (int j = 0; j < 8; j++)
#pragma unroll
            for (int q = 0; q < 4; q++) acc[i][j][q] = 0.f;

    // 3072 16B units per chunk: A(1024) + Bh(1024) + Bl(1024); 12 per thread
    auto load_chunk = [&](int ch, int stage) {
        const int k0 = ch * 64;
        const uint32_t sbase = sb + stage * STAGE_B;
#pragma unroll
        for (int u = 0; u < 12; u++) {
            int idx = tid + u * 256;
            int mat = idx >> 10;
            int wi  = idx & 1023;
            int r = wi >> 3, c = wi & 7;
            uint32_t so = (uint32_t)(mat * TILE_B + r * RSTR + c * 16);
            const __half* src = (mat == 0) ? (A  + (size_t)(brow + r) * K + k0 + c * 8)
                              : (mat == 1) ? (Bh + (size_t)(bcol + r) * K + k0 + c * 8)
                                           : (Bl + (size_t)(bcol + r) * K + k0 + c * 8);
            cp16(sbase + so, src);
        }
        asm volatile("cp.async.commit_group;" ::: "memory");
    };

    load_chunk(0, 0);

    for (int ch = 0; ch < nch; ch++) {
        if (ch + 1 < nch) {
            load_chunk(ch + 1, (ch + 1) & 1);
            asm volatile("cp.async.wait_group 1;" ::: "memory");
        } else {
            asm volatile("cp.async.wait_group 0;" ::: "memory");
        }
        __syncthreads();

        const uint32_t sbase = sb + (ch & 1) * STAGE_B;
        const uint32_t abase = sbase;
        const uint32_t bhb   = sbase + TILE_B;
        const uint32_t blb   = sbase + 2 * TILE_B;

#pragma unroll
        for (int ks = 0; ks < 4; ks++) {
            uint32_t a[2][4];
            const uint32_t arow = (uint32_t)(wm * 32 + (lane & 15));
            const uint32_t akb  = (uint32_t)(ks * 32 + ((lane >> 4) & 1) * 16);
#pragma unroll
            for (int tm = 0; tm < 2; tm++) {
                uint32_t off = (arow + tm * 16) * RSTR + akb;
                ldsm4(a[tm][0], a[tm][1], a[tm][2], a[tm][3], abase + off);
            }
            uint32_t b_h[8][2], b_l[8][2];
            const uint32_t nrow0 = (uint32_t)(wn * 64 + (lane & 7) + ((lane >> 4) & 1) * 8);
            const uint32_t bkb   = (uint32_t)(ks * 32 + ((lane >> 3) & 1) * 16);
#pragma unroll
            for (int tp = 0; tp < 4; tp++) {
                uint32_t off = (nrow0 + tp * 16) * RSTR + bkb;
                ldsm4(b_h[tp * 2][0], b_h[tp * 2][1], b_h[tp * 2 + 1][0], b_h[tp * 2 + 1][1], bhb + off);
                ldsm4(b_l[tp * 2][0], b_l[tp * 2][1], b_l[tp * 2 + 1][0], b_l[tp * 2 + 1][1], blb + off);
            }
#pragma unroll
            for (int tm = 0; tm < 2; tm++)
#pragma unroll
                for (int tn = 0; tn < 8; tn++) {
                    mma_f16(acc[tm][tn], a[tm], b_h[tn]);
                    mma_f16(acc[tm][tn], a[tm], b_l[tn]);
                }
        }
        __syncthreads();
    }

    // epilogue: bias (+ReLU); fp16 activation or fp32 P output
#pragma unroll
    for (int tm = 0; tm < 2; tm++) {
#pragma unroll
        for (int tn = 0; tn < 8; tn++) {
            int n = bcol + wn * 64 + tn * 8 + 2 * (lane & 3);
            if (n >= Nreal) continue;
            float bb0 = bias[n], bb1 = bias[n + 1];
#pragma unroll
            for (int half = 0; half < 2; half++) {
                int m = brow + wm * 32 + tm * 16 + (lane >> 2) + half * 8;
                float v0 = acc[tm][tn][half * 2 + 0] + bb0;
                float v1 = acc[tm][tn][half * 2 + 1] + bb1;
                if (RELU) { v0 = fmaxf(v0, 0.f); v1 = fmaxf(v1, 0.f); }
                if (F32OUT) {
                    *reinterpret_cast<float2*>(Cf + (size_t)m * ldc + n) = make_float2(v0, v1);
                } else {
                    __half2 hv = __floats2half2_rn(v0, v1);
                    *reinterpret_cast<__half2*>(Ch + (size_t)m * ldc + n) = hv;
                }
            }
        }
    }
}

// ================= epilogue (lpaff folded in) =================
__global__ void k_final(const float* __restrict__ stds, float* __restrict__ out) {
    __shared__ float s_lp;
    if (threadIdx.x < 32) {
        float v = logf(10.0f * stds[threadIdx.x]);
#pragma unroll
        for (int o = 16; o > 0; o >>= 1) v += __shfl_down_sync(0xffffffffu, v, o);
        if (threadIdx.x == 0) s_lp = -v;
    }
    __syncthreads();
    int n = blockIdx.x * blockDim.x + threadIdx.x;
    if (n >= NS) return;
    float ss = 0.f;
#pragma unroll
    for (int d = 0; d < DD; d++) { float z = g_z[n * DD + d]; ss = fmaf(z, z, ss); }
    float ls = 0.f;
#pragma unroll
    for (int j = 0; j < SPLITD; j++) ls += g_ladj[n * SPLITD + j];
    out[n] = -0.5f * ss - 0.5f * (float)DD * LOG2PI_F + ls + s_lp;
}

// ================= launch =================
extern "C" void kernel_launch(void* const* d_in, const int* in_sizes, int n_in,
                              void* d_out, int out_size) {
    const float* data  = (const float*)d_in[0];
    const float* means = (const float*)d_in[1];
    const float* stds  = (const float*)d_in[2];

    const float* tw[2]  = { (const float*)d_in[13], (const float*)d_in[3] };
    const float* th[2]  = { (const float*)d_in[14], (const float*)d_in[4] };
    const float* td[2]  = { (const float*)d_in[15], (const float*)d_in[5] };
    const float* tl[2]  = { (const float*)d_in[16], (const float*)d_in[6] };
    const float* tW1[2] = { (const float*)d_in[17], (const float*)d_in[7] };
    const float* tb1[2] = { (const float*)d_in[18], (const float*)d_in[8] };
    const float* tW2[2] = { (const float*)d_in[19], (const float*)d_in[9] };
    const float* tb2[2] = { (const float*)d_in[20], (const float*)d_in[10] };
    const float* tW3[2] = { (const float*)d_in[21], (const float*)d_in[11] };
    const float* tb3[2] = { (const float*)d_in[22], (const float*)d_in[12] };

    float* out = (float*)d_out;

    __half *x1, *H1, *H2, *W1th, *W1tl, *W2th, *W2tl, *W3th, *W3tl;
    float* pP;
    cudaGetSymbolAddress((void**)&x1,  g_x1);
    cudaGetSymbolAddress((void**)&H1,  g_H1);
    cudaGetSymbolAddress((void**)&H2,  g_H2);
    cudaGetSymbolAddress((void**)&W1th, g_W1th); cudaGetSymbolAddress((void**)&W1tl, g_W1tl);
    cudaGetSymbolAddress((void**)&W2th, g_W2th); cudaGetSymbolAddress((void**)&W2tl, g_W2tl);
    cudaGetSymbolAddress((void**)&W3th, g_W3th); cudaGetSymbolAddress((void**)&W3tl, g_W3tl);
    cudaGetSymbolAddress((void**)&pP, g_P);

    cudaFuncSetAttribute(hgemm<true,  false>, cudaFuncAttributeMaxDynamicSharedMemorySize, SM_TOTAL);
    cudaFuncSetAttribute(hgemm<false, true >, cudaFuncAttributeMaxDynamicSharedMemorySize, SM_TOTAL);

    const int splineBlocks = (NS * SPLITD) / 256;
    dim3 g12(NP12 / 128, NS / 128);  // (3, 256)
    dim3 g3 (NP3  / 128, NS / 128);  // (8, 256)
    const int prepBlocks = (PREP_TOT + 255) / 256;

    for (int L = 0; L < 2; L++) {   // L=0 -> t2 (applied first), L=1 -> t1
        k_prepall<<<prepBlocks, 256>>>(tW1[L], tW2[L], tW3[L]);

        if (L == 0)
            k_spline1<true ><<<splineBlocks, 256>>>(data, means, stds, tw[L], th[L], td[L], tl[L]);
        else
            k_spline1<false><<<splineBlocks, 256>>>(data, means, stds, tw[L], th[L], td[L], tl[L]);

        hgemm<true,  false><<<g12, 256, SM_TOTAL>>>(x1, W1th, W1tl, tb1[L],
                                                    KP1, HID, HID, H1, nullptr);
        hgemm<true,  false><<<g12, 256, SM_TOTAL>>>(H1, W2th, W2tl, tb2[L],
                                                    HID, HID, HID, H2, nullptr);
        hgemm<false, true ><<<g3,  256, SM_TOTAL>>>(H2, W3th, W3tl, tb3[L],
                                                    HID, POUT, POUT, nullptr, pP);

        k_spline2<<<splineBlocks, 256>>>();
    }

    k_final<<<NS / 256, 256>>>(stds, out);
}

// round 5
// speedup vs baseline: 3.7344x; 1.0397x over previous
#include <cuda_runtime.h>
#include <cuda_fp16.h>
#include <math.h>
#include <stdint.h>

#define NS    32768
#define DD    32
#define SPLITD 16
#define BINSN 16
#define HID   320
#define POUT  1008
#define LOG2PI_F 1.8378770664093453f

// padded GEMM dims
#define KP1   64      // GEMM1 K padded (real 16)
#define NP12  384     // GEMM1/2 N padded (real 320)
#define NP3   1024    // GEMM3 N padded (real 1008)

// ================= scratch (device globals; zero-initialized at load) =================
__device__ float g_z[NS * DD];
__device__ float g_ladj[NS * SPLITD];
__device__ float g_P[(size_t)NS * POUT];

__device__ __half g_x1[NS * KP1];     // pad cols stay zero forever
__device__ __half g_H1[NS * HID];
__device__ __half g_H2[NS * HID];

__device__ __half g_W1th[NP12 * KP1];
__device__ __half g_W1tl[NP12 * KP1];
__device__ __half g_W2th[NP12 * HID];
__device__ __half g_W2tl[NP12 * HID];
__device__ __half g_W3th[(size_t)NP3 * HID];
__device__ __half g_W3tl[(size_t)NP3 * HID];

// ================= helpers =================
__device__ __forceinline__ uint32_t smem_u32(const void* p) {
    uint32_t a;
    asm("{ .reg .u64 t; cvta.to.shared.u64 t, %1; cvt.u32.u64 %0, t; }" : "=r"(a) : "l"(p));
    return a;
}
__device__ __forceinline__ void cp16(uint32_t dst, const void* src) {
    asm volatile("cp.async.cg.shared.global [%0], [%1], 16;" :: "r"(dst), "l"(src));
}
__device__ __forceinline__ void ldsm4(uint32_t& r0, uint32_t& r1, uint32_t& r2, uint32_t& r3, uint32_t a) {
    asm volatile("ldmatrix.sync.aligned.m8n8.x4.shared.b16 {%0,%1,%2,%3}, [%4];"
                 : "=r"(r0), "=r"(r1), "=r"(r2), "=r"(r3) : "r"(a));
}
__device__ __forceinline__ void mma_f16(float* c, const uint32_t* a, const uint32_t* b) {
    asm volatile("mma.sync.aligned.m16n8k16.row.col.f32.f16.f16.f32 "
                 "{%0,%1,%2,%3}, {%4,%5,%6,%7}, {%8,%9}, {%0,%1,%2,%3};"
                 : "+f"(c[0]), "+f"(c[1]), "+f"(c[2]), "+f"(c[3])
                 : "r"(a[0]), "r"(a[1]), "r"(a[2]), "r"(a[3]), "r"(b[0]), "r"(b[1]));
}

// ================= weight prep (one launch per layer) =================
#define SEG1 (NP12 * KP1)
#define SEG2 (NP12 * HID)
#define SEG3 (NP3 * HID)
#define PREP_TOT (SEG1 + SEG2 + SEG3)

__global__ void k_prepall(const float* __restrict__ W1, const float* __restrict__ W2,
                          const float* __restrict__ W3) {
    int idx = blockIdx.x * blockDim.x + threadIdx.x;
    const float* W; __half *Th, *Tl; int K, N, Kp;
    if (idx < SEG1)              { W = W1; Th = g_W1th; Tl = g_W1tl; K = SPLITD; N = HID;  Kp = KP1; }
    else if (idx < SEG1 + SEG2)  { idx -= SEG1; W = W2; Th = g_W2th; Tl = g_W2tl; K = HID; N = HID;  Kp = HID; }
    else if (idx < PREP_TOT)     { idx -= SEG1 + SEG2; W = W3; Th = g_W3th; Tl = g_W3tl; K = HID; N = POUT; Kp = HID; }
    else return;
    int n = idx / Kp, k = idx - n * Kp;
    float v = (n < N && k < K) ? W[(size_t)k * N + n] : 0.0f;
    __half hi = __float2half_rn(v);
    Th[idx] = hi;
    Tl[idx] = __float2half_rn(v - __half2float(hi));
}

// ================= spline inverse =================
__device__ __forceinline__ float softplusf(float v) {
    return fmaxf(v, 0.0f) + log1pf(expf(-fabsf(v)));
}

__device__ __forceinline__ void rls_inv(
    float y,
    const float* __restrict__ wr, const float* __restrict__ hr,
    const float* __restrict__ dr, const float* __restrict__ lr,
    float& xo, float& lo_)
{
    const float BD = 3.0f;
    float w[BINSN], h[BINSN];
#pragma unroll
    for (int b = 0; b < BINSN; b++) { w[b] = wr[b]; h[b] = hr[b]; }

    bool inside = (y >= -BD) && (y <= BD);
    float yc = fminf(fmaxf(y, -BD), BD);

    float hm = h[0];
#pragma unroll
    for (int b = 1; b < BINSN; b++) hm = fmaxf(hm, h[b]);
    float hs = 0.f;
#pragma unroll
    for (int b = 0; b < BINSN; b++) { h[b] = expf(h[b] - hm); hs += h[b]; }
    float hscale = 0.984f / hs;

    int idx = 0; float ich = -BD, ih = 0.f;
    {
        float prev = -BD, cs = 0.f;
#pragma unroll
        for (int b = 0; b < BINSN; b++) {
            float hb = 0.001f + hscale * h[b];
            cs += hb;
            float e = (b == BINSN - 1) ? BD : fmaf(6.0f, cs, -3.0f);
            if (yc >= prev) { idx = b; ich = prev; ih = e - prev; }
            prev = e;
        }
    }

    float wm = w[0];
#pragma unroll
    for (int b = 1; b < BINSN; b++) wm = fmaxf(wm, w[b]);
    float ws = 0.f;
#pragma unroll
    for (int b = 0; b < BINSN; b++) { w[b] = expf(w[b] - wm); ws += w[b]; }
    float wscale = 0.984f / ws;

    float icw = -BD, iw = 0.f;
    {
        float prev = -BD, cs = 0.f;
#pragma unroll
        for (int b = 0; b < BINSN; b++) {
            float wb_ = 0.001f + wscale * w[b];
            cs += wb_;
            float e = (b == BINSN - 1) ? BD : fmaf(6.0f, cs, -3.0f);
            if (b == idx) { icw = prev; iw = e - prev; }
            prev = e;
        }
    }

    float idv   = (idx == 0)         ? 0.999f : (0.001f + softplusf(dr[idx - 1]));
    float idvp1 = (idx == BINSN - 1) ? 0.999f : (0.001f + softplusf(dr[idx]));
    float il    = 0.025f + 0.95f / (1.0f + expf(-lr[idx]));

    float idel = ih / iw;
    float wb   = sqrtf(idv / idvp1);
    float wc   = (il * idv + (1.0f - il) * wb * idvp1) / idel;
    float ya = ich, yb = ih + ich;
    float ym = ((1.0f - il) * ya + il * wb * yb) / ((1.0f - il) + il * wb);

    bool left = (yc <= ym);
    float num, den, dnum;
    if (left) {
        num  = il * (ya - yc);
        den  = (wc - 1.0f) * yc + ya - wc * ym;
        dnum = wc * il * (ym - ya) * iw;
    } else {
        num  = (wc - il * wb) * yc + il * wb * yb - wc * ym;
        den  = (wc - wb) * yc + wb * yb - wc * ym;
        dnum = wb * wc * (1.0f - il) * (yb - ym) * iw;
    }
    float x  = num / den * iw + icw;
    float la = logf(dnum) - 2.0f * logf(fabsf(den));

    xo  = inside ? x  : y;
    lo_ = inside ? la : 0.0f;
}

// spline2 on second half from P row; returns x2, accumulated ladj
__device__ __forceinline__ void spline2_step(int n, int j, float& x2, float& ladj_acc) {
    float y = g_z[n * DD + SPLITD + j];
    const float* pr = g_P + (size_t)n * POUT;
    float la;
    rls_inv(y,
            pr + j * BINSN,
            pr + 256 + j * BINSN,
            pr + 512 + j * (BINSN - 1),
            pr + 752 + j * BINSN,
            x2, la);
    ladj_acc += la;
}

// first kernel: affine prelude + spline1 of layer 0
__global__ void k_first(const float* __restrict__ data,
                        const float* __restrict__ means,
                        const float* __restrict__ stds,
                        const float* __restrict__ wp, const float* __restrict__ hp,
                        const float* __restrict__ dp, const float* __restrict__ lp) {
    int i = blockIdx.x * blockDim.x + threadIdx.x;
    if (i >= NS * SPLITD) return;
    int n = i >> 4, j = i & 15;
    float y  = (data[n * DD + j]      - means[j])      / (10.0f * stds[j]);
    float y2 = (data[n * DD + j + 16] - means[j + 16]) / (10.0f * stds[j + 16]);
    g_z[n * DD + j + 16] = y2;
    float x, la;
    rls_inv(y, wp + j * BINSN, hp + j * BINSN, dp + j * (BINSN - 1), lp + j * BINSN, x, la);
    g_z[n * DD + j] = x;
    g_x1[n * KP1 + j] = __float2half_rn(x);
    g_ladj[i] = la;
}

// mid kernel: spline2 of layer L (from P) + spline1 of layer L+1 (fixed params)
__global__ void k_mid(const float* __restrict__ wp, const float* __restrict__ hp,
                      const float* __restrict__ dp, const float* __restrict__ lp) {
    int i = blockIdx.x * blockDim.x + threadIdx.x;
    if (i >= NS * SPLITD) return;
    int n = i >> 4, j = i & 15;
    float ladj = g_ladj[i];
    float x2;
    spline2_step(n, j, x2, ladj);
    g_z[n * DD + SPLITD + j] = x2;

    float y1 = g_z[n * DD + j];
    float x1, la1;
    rls_inv(y1, wp + j * BINSN, hp + j * BINSN, dp + j * (BINSN - 1), lp + j * BINSN, x1, la1);
    g_z[n * DD + j] = x1;
    g_x1[n * KP1 + j] = __float2half_rn(x1);
    g_ladj[i] = ladj + la1;
}

// last kernel: spline2 of final layer + Gaussian base + lpaff reduction -> out
__global__ void k_last(const float* __restrict__ stds, float* __restrict__ out) {
    __shared__ float s_lp;
    if (threadIdx.x < 32) {
        float v = logf(10.0f * stds[threadIdx.x]);
#pragma unroll
        for (int o = 16; o > 0; o >>= 1) v += __shfl_down_sync(0xffffffffu, v, o);
        if (threadIdx.x == 0) s_lp = -v;
    }
    __syncthreads();
    int i = blockIdx.x * blockDim.x + threadIdx.x;
    int n = i >> 4, j = i & 15;
    float ladj = g_ladj[i];
    float x2;
    spline2_step(n, j, x2, ladj);
    float z1 = g_z[n * DD + j];
    float ss = fmaf(z1, z1, x2 * x2);
#pragma unroll
    for (int o = 1; o < 16; o <<= 1) {
        ss   += __shfl_xor_sync(0xffffffffu, ss, o);
        ladj += __shfl_xor_sync(0xffffffffu, ladj, o);
    }
    if ((threadIdx.x & 15) == 0)
        out[n] = -0.5f * ss - 0.5f * (float)DD * LOG2PI_F + ladj + s_lp;
}

// ================= HMMA fp16 weight-split GEMM =================
// CTA 128x128, 4 warps, warp tile 64x64. B stored [Npad,K] K-major, split hi+lo fp16.
// smem: rows of 64 fp16, stride 144B (conflict-free ldmatrix). BK=64, 2 stages.
#define RSTR    144
#define TILE_B  (128 * RSTR)          // 18432
#define STAGE_B (3 * TILE_B)          // 55296
#define SM_TOTAL (2 * STAGE_B)        // 110592

template <bool RELU, bool F32OUT>
__global__ void __launch_bounds__(128) hgemm(
    const __half* __restrict__ A,
    const __half* __restrict__ Bh, const __half* __restrict__ Bl,
    const float* __restrict__ bias,
    int K, int Nreal, int ldc,
    __half* __restrict__ Ch, float* __restrict__ Cf)
{
    extern __shared__ char smem[];
    const uint32_t sb = smem_u32(smem);
    const int tid = threadIdx.x;
    const int wid = tid >> 5, lane = tid & 31;
    const int wm = wid >> 1, wn = wid & 1;          // 2x2 warp grid, warp tile 64x64

    const int brow = blockIdx.y * 128;
    const int bcol = blockIdx.x * 128;
    const int nch = K >> 6;

    float acc[4][8][4];
#pragma unroll
    for (int i = 0; i < 4; i++)
#pragma unroll
        for (int j = 0; j < 8; j++)
#pragma unroll
            for (int q = 0; q < 4; q++) acc[i][j][q] = 0.f;

    // 3072 16B units per chunk: A(1024) + Bh(1024) + Bl(1024); 24 per thread
    auto load_chunk = [&](int ch, int stage) {
        const int k0 = ch * 64;
        const uint32_t sbase = sb + stage * STAGE_B;
#pragma unroll
        for (int u = 0; u < 24; u++) {
            int idx = tid + u * 128;
            int mat = idx >> 10;
            int wi  = idx & 1023;
            int r = wi >> 3, c = wi & 7;
            uint32_t so = (uint32_t)(mat * TILE_B + r * RSTR + c * 16);
            const __half* src = (mat == 0) ? (A  + (size_t)(brow + r) * K + k0 + c * 8)
                              : (mat == 1) ? (Bh + (size_t)(bcol + r) * K + k0 + c * 8)
                                           : (Bl + (size_t)(bcol + r) * K + k0 + c * 8);
            cp16(sbase + so, src);
        }
        asm volatile("cp.async.commit_group;" ::: "memory");
    };

    load_chunk(0, 0);

    for (int ch = 0; ch < nch; ch++) {
        if (ch + 1 < nch) {
            load_chunk(ch + 1, (ch + 1) & 1);
            asm volatile("cp.async.wait_group 1;" ::: "memory");
        } else {
            asm volatile("cp.async.wait_group 0;" ::: "memory");
        }
        __syncthreads();

        const uint32_t sbase = sb + (ch & 1) * STAGE_B;
        const uint32_t abase = sbase;
        const uint32_t bhb   = sbase + TILE_B;
        const uint32_t blb   = sbase + 2 * TILE_B;

#pragma unroll
        for (int ks = 0; ks < 4; ks++) {
            uint32_t a[4][4];
            const uint32_t arow = (uint32_t)(wm * 64 + (lane & 15));
            const uint32_t akb  = (uint32_t)(ks * 32 + ((lane >> 4) & 1) * 16);
#pragma unroll
            for (int tm = 0; tm < 4; tm++) {
                uint32_t off = (arow + tm * 16) * RSTR + akb;
                ldsm4(a[tm][0], a[tm][1], a[tm][2], a[tm][3], abase + off);
            }
            uint32_t b_h[8][2], b_l[8][2];
            const uint32_t nrow0 = (uint32_t)(wn * 64 + (lane & 7) + ((lane >> 4) & 1) * 8);
            const uint32_t bkb   = (uint32_t)(ks * 32 + ((lane >> 3) & 1) * 16);
#pragma unroll
            for (int tp = 0; tp < 4; tp++) {
                uint32_t off = (nrow0 + tp * 16) * RSTR + bkb;
                ldsm4(b_h[tp * 2][0], b_h[tp * 2][1], b_h[tp * 2 + 1][0], b_h[tp * 2 + 1][1], bhb + off);
                ldsm4(b_l[tp * 2][0], b_l[tp * 2][1], b_l[tp * 2 + 1][0], b_l[tp * 2 + 1][1], blb + off);
            }
#pragma unroll
            for (int tm = 0; tm < 4; tm++)
#pragma unroll
                for (int tn = 0; tn < 8; tn++) {
                    mma_f16(acc[tm][tn], a[tm], b_h[tn]);
                    mma_f16(acc[tm][tn], a[tm], b_l[tn]);
                }
        }
        __syncthreads();
    }

    // epilogue: bias (+ReLU); fp16 activation or fp32 P output
#pragma unroll
    for (int tm = 0; tm < 4; tm++) {
#pragma unroll
        for (int tn = 0; tn < 8; tn++) {
            int n = bcol + wn * 64 + tn * 8 + 2 * (lane & 3);
            if (n >= Nreal) continue;
            float bb0 = bias[n], bb1 = bias[n + 1];
#pragma unroll
            for (int half = 0; half < 2; half++) {
                int m = brow + wm * 64 + tm * 16 + (lane >> 2) + half * 8;
                float v0 = acc[tm][tn][half * 2 + 0] + bb0;
                float v1 = acc[tm][tn][half * 2 + 1] + bb1;
                if (RELU) { v0 = fmaxf(v0, 0.f); v1 = fmaxf(v1, 0.f); }
                if (F32OUT) {
                    *reinterpret_cast<float2*>(Cf + (size_t)m * ldc + n) = make_float2(v0, v1);
                } else {
                    __half2 hv = __floats2half2_rn(v0, v1);
                    *reinterpret_cast<__half2*>(Ch + (size_t)m * ldc + n) = hv;
                }
            }
        }
    }
}

// ================= launch =================
extern "C" void kernel_launch(void* const* d_in, const int* in_sizes, int n_in,
                              void* d_out, int out_size) {
    const float* data  = (const float*)d_in[0];
    const float* means = (const float*)d_in[1];
    const float* stds  = (const float*)d_in[2];

    const float* tw[2]  = { (const float*)d_in[13], (const float*)d_in[3] };
    const float* th[2]  = { (const float*)d_in[14], (const float*)d_in[4] };
    const float* td[2]  = { (const float*)d_in[15], (const float*)d_in[5] };
    const float* tl[2]  = { (const float*)d_in[16], (const float*)d_in[6] };
    const float* tW1[2] = { (const float*)d_in[17], (const float*)d_in[7] };
    const float* tb1[2] = { (const float*)d_in[18], (const float*)d_in[8] };
    const float* tW2[2] = { (const float*)d_in[19], (const float*)d_in[9] };
    const float* tb2[2] = { (const float*)d_in[20], (const float*)d_in[10] };
    const float* tW3[2] = { (const float*)d_in[21], (const float*)d_in[11] };
    const float* tb3[2] = { (const float*)d_in[22], (const float*)d_in[12] };

    float* out = (float*)d_out;

    __half *x1, *H1, *H2, *W1th, *W1tl, *W2th, *W2tl, *W3th, *W3tl;
    float* pP;
    cudaGetSymbolAddress((void**)&x1,  g_x1);
    cudaGetSymbolAddress((void**)&H1,  g_H1);
    cudaGetSymbolAddress((void**)&H2,  g_H2);
    cudaGetSymbolAddress((void**)&W1th, g_W1th); cudaGetSymbolAddress((void**)&W1tl, g_W1tl);
    cudaGetSymbolAddress((void**)&W2th, g_W2th); cudaGetSymbolAddress((void**)&W2tl, g_W2tl);
    cudaGetSymbolAddress((void**)&W3th, g_W3th); cudaGetSymbolAddress((void**)&W3tl, g_W3tl);
    cudaGetSymbolAddress((void**)&pP, g_P);

    cudaFuncSetAttribute(hgemm<true,  false>, cudaFuncAttributeMaxDynamicSharedMemorySize, SM_TOTAL);
    cudaFuncSetAttribute(hgemm<false, true >, cudaFuncAttributeMaxDynamicSharedMemorySize, SM_TOTAL);

    const int splineBlocks = (NS * SPLITD) / 256;
    dim3 g12(NP12 / 128, NS / 128);  // (3, 256)
    dim3 g3 (NP3  / 128, NS / 128);  // (8, 256)
    const int prepBlocks = (PREP_TOT + 255) / 256;

    for (int L = 0; L < 2; L++) {   // L=0 -> t2 (applied first), L=1 -> t1
        k_prepall<<<prepBlocks, 256>>>(tW1[L], tW2[L], tW3[L]);

        if (L == 0)
            k_first<<<splineBlocks, 256>>>(data, means, stds, tw[0], th[0], td[0], tl[0]);

        hgemm<true,  false><<<g12, 128, SM_TOTAL>>>(x1, W1th, W1tl, tb1[L],
                                                    KP1, HID, HID, H1, nullptr);
        hgemm<true,  false><<<g12, 128, SM_TOTAL>>>(H1, W2th, W2tl, tb2[L],
                                                    HID, HID, HID, H2, nullptr);
        hgemm<false, true ><<<g3,  128, SM_TOTAL>>>(H2, W3th, W3tl, tb3[L],
                                                    HID, POUT, POUT, nullptr, pP);

        if (L == 0)
            k_mid<<<splineBlocks, 256>>>(tw[1], th[1], td[1], tl[1]);
        else
            k_last<<<splineBlocks, 256>>>(stds, out);
    }
}

// round 6
// speedup vs baseline: 4.9875x; 1.3356x over previous
#include <cuda_runtime.h>
#include <cuda_fp16.h>
#include <math.h>
#include <stdint.h>

#define NS    32768
#define DD    32
#define SPLITD 16
#define BINSN 16
#define HID   320
#define POUT  1008
#define LOG2PI_F 1.8378770664093453f

// padded GEMM dims
#define KP1   64      // GEMM1 K padded (real 16)
#define NP12  384     // GEMM1/2 N padded (real 320)
#define NP3   1024    // GEMM3 N padded (real 1008)

// ================= scratch (device globals; zero-initialized at load) =================
__device__ float g_z[NS * DD];
__device__ float g_ladj[NS * SPLITD];
__device__ float g_P[(size_t)NS * POUT];

__device__ __half g_x1[NS * KP1];     // pad cols stay zero forever
__device__ __half g_H1[NS * HID];
__device__ __half g_H2[NS * HID];

__device__ __half g_W1t[NP12 * KP1];
__device__ __half g_W2t[NP12 * HID];
__device__ __half g_W3t[(size_t)NP3 * HID];

// ================= helpers =================
__device__ __forceinline__ uint32_t smem_u32(const void* p) {
    uint32_t a;
    asm("{ .reg .u64 t; cvta.to.shared.u64 t, %1; cvt.u32.u64 %0, t; }" : "=r"(a) : "l"(p));
    return a;
}
__device__ __forceinline__ void cp16(uint32_t dst, const void* src) {
    asm volatile("cp.async.cg.shared.global [%0], [%1], 16;" :: "r"(dst), "l"(src));
}
__device__ __forceinline__ void ldsm4(uint32_t& r0, uint32_t& r1, uint32_t& r2, uint32_t& r3, uint32_t a) {
    asm volatile("ldmatrix.sync.aligned.m8n8.x4.shared.b16 {%0,%1,%2,%3}, [%4];"
                 : "=r"(r0), "=r"(r1), "=r"(r2), "=r"(r3) : "r"(a));
}
__device__ __forceinline__ void mma_f16(float* c, const uint32_t* a, const uint32_t* b) {
    asm volatile("mma.sync.aligned.m16n8k16.row.col.f32.f16.f16.f32 "
                 "{%0,%1,%2,%3}, {%4,%5,%6,%7}, {%8,%9}, {%0,%1,%2,%3};"
                 : "+f"(c[0]), "+f"(c[1]), "+f"(c[2]), "+f"(c[3])
                 : "r"(a[0]), "r"(a[1]), "r"(a[2]), "r"(a[3]), "r"(b[0]), "r"(b[1]));
}

// ================= weight prep (one launch per layer) =================
#define SEG1 (NP12 * KP1)
#define SEG2 (NP12 * HID)
#define SEG3 (NP3 * HID)
#define PREP_TOT (SEG1 + SEG2 + SEG3)

__global__ void k_prepall(const float* __restrict__ W1, const float* __restrict__ W2,
                          const float* __restrict__ W3) {
    int idx = blockIdx.x * blockDim.x + threadIdx.x;
    const float* W; __half* T; int K, N, Kp;
    if (idx < SEG1)              { W = W1; T = g_W1t; K = SPLITD; N = HID;  Kp = KP1; }
    else if (idx < SEG1 + SEG2)  { idx -= SEG1; W = W2; T = g_W2t; K = HID; N = HID;  Kp = HID; }
    else if (idx < PREP_TOT)     { idx -= SEG1 + SEG2; W = W3; T = g_W3t; K = HID; N = POUT; Kp = HID; }
    else return;
    int n = idx / Kp, k = idx - n * Kp;
    float v = (n < N && k < K) ? W[(size_t)k * N + n] : 0.0f;
    T[idx] = __float2half_rn(v);
}

// ================= spline inverse =================
__device__ __forceinline__ float softplusf(float v) {
    return fmaxf(v, 0.0f) + log1pf(expf(-fabsf(v)));
}

__device__ __forceinline__ void rls_inv(
    float y,
    const float* __restrict__ wr, const float* __restrict__ hr,
    const float* __restrict__ dr, const float* __restrict__ lr,
    float& xo, float& lo_)
{
    const float BD = 3.0f;
    float w[BINSN], h[BINSN];
#pragma unroll
    for (int b = 0; b < BINSN; b++) { w[b] = wr[b]; h[b] = hr[b]; }

    bool inside = (y >= -BD) && (y <= BD);
    float yc = fminf(fmaxf(y, -BD), BD);

    float hm = h[0];
#pragma unroll
    for (int b = 1; b < BINSN; b++) hm = fmaxf(hm, h[b]);
    float hs = 0.f;
#pragma unroll
    for (int b = 0; b < BINSN; b++) { h[b] = expf(h[b] - hm); hs += h[b]; }
    float hscale = 0.984f / hs;

    int idx = 0; float ich = -BD, ih = 0.f;
    {
        float prev = -BD, cs = 0.f;
#pragma unroll
        for (int b = 0; b < BINSN; b++) {
            float hb = 0.001f + hscale * h[b];
            cs += hb;
            float e = (b == BINSN - 1) ? BD : fmaf(6.0f, cs, -3.0f);
            if (yc >= prev) { idx = b; ich = prev; ih = e - prev; }
            prev = e;
        }
    }

    float wm = w[0];
#pragma unroll
    for (int b = 1; b < BINSN; b++) wm = fmaxf(wm, w[b]);
    float ws = 0.f;
#pragma unroll
    for (int b = 0; b < BINSN; b++) { w[b] = expf(w[b] - wm); ws += w[b]; }
    float wscale = 0.984f / ws;

    float icw = -BD, iw = 0.f;
    {
        float prev = -BD, cs = 0.f;
#pragma unroll
        for (int b = 0; b < BINSN; b++) {
            float wb_ = 0.001f + wscale * w[b];
            cs += wb_;
            float e = (b == BINSN - 1) ? BD : fmaf(6.0f, cs, -3.0f);
            if (b == idx) { icw = prev; iw = e - prev; }
            prev = e;
        }
    }

    float idv   = (idx == 0)         ? 0.999f : (0.001f + softplusf(dr[idx - 1]));
    float idvp1 = (idx == BINSN - 1) ? 0.999f : (0.001f + softplusf(dr[idx]));
    float il    = 0.025f + 0.95f / (1.0f + expf(-lr[idx]));

    float idel = ih / iw;
    float wb   = sqrtf(idv / idvp1);
    float wc   = (il * idv + (1.0f - il) * wb * idvp1) / idel;
    float ya = ich, yb = ih + ich;
    float ym = ((1.0f - il) * ya + il * wb * yb) / ((1.0f - il) + il * wb);

    bool left = (yc <= ym);
    float num, den, dnum;
    if (left) {
        num  = il * (ya - yc);
        den  = (wc - 1.0f) * yc + ya - wc * ym;
        dnum = wc * il * (ym - ya) * iw;
    } else {
        num  = (wc - il * wb) * yc + il * wb * yb - wc * ym;
        den  = (wc - wb) * yc + wb * yb - wc * ym;
        dnum = wb * wc * (1.0f - il) * (yb - ym) * iw;
    }
    float x  = num / den * iw + icw;
    float la = logf(dnum) - 2.0f * logf(fabsf(den));

    xo  = inside ? x  : y;
    lo_ = inside ? la : 0.0f;
}

// spline2 on second half from P row; returns x2, accumulated ladj
__device__ __forceinline__ void spline2_step(int n, int j, float& x2, float& ladj_acc) {
    float y = g_z[n * DD + SPLITD + j];
    const float* pr = g_P + (size_t)n * POUT;
    float la;
    rls_inv(y,
            pr + j * BINSN,
            pr + 256 + j * BINSN,
            pr + 512 + j * (BINSN - 1),
            pr + 752 + j * BINSN,
            x2, la);
    ladj_acc += la;
}

// first kernel: affine prelude + spline1 of layer 0
__global__ void k_first(const float* __restrict__ data,
                        const float* __restrict__ means,
                        const float* __restrict__ stds,
                        const float* __restrict__ wp, const float* __restrict__ hp,
                        const float* __restrict__ dp, const float* __restrict__ lp) {
    int i = blockIdx.x * blockDim.x + threadIdx.x;
    if (i >= NS * SPLITD) return;
    int n = i >> 4, j = i & 15;
    float y  = (data[n * DD + j]      - means[j])      / (10.0f * stds[j]);
    float y2 = (data[n * DD + j + 16] - means[j + 16]) / (10.0f * stds[j + 16]);
    g_z[n * DD + j + 16] = y2;
    float x, la;
    rls_inv(y, wp + j * BINSN, hp + j * BINSN, dp + j * (BINSN - 1), lp + j * BINSN, x, la);
    g_z[n * DD + j] = x;
    g_x1[n * KP1 + j] = __float2half_rn(x);
    g_ladj[i] = la;
}

// mid kernel: spline2 of layer L (from P) + spline1 of layer L+1 (fixed params)
__global__ void k_mid(const float* __restrict__ wp, const float* __restrict__ hp,
                      const float* __restrict__ dp, const float* __restrict__ lp) {
    int i = blockIdx.x * blockDim.x + threadIdx.x;
    if (i >= NS * SPLITD) return;
    int n = i >> 4, j = i & 15;
    float ladj = g_ladj[i];
    float x2;
    spline2_step(n, j, x2, ladj);
    g_z[n * DD + SPLITD + j] = x2;

    float y1 = g_z[n * DD + j];
    float x1, la1;
    rls_inv(y1, wp + j * BINSN, hp + j * BINSN, dp + j * (BINSN - 1), lp + j * BINSN, x1, la1);
    g_z[n * DD + j] = x1;
    g_x1[n * KP1 + j] = __float2half_rn(x1);
    g_ladj[i] = ladj + la1;
}

// last kernel: spline2 of final layer + Gaussian base + lpaff reduction -> out
__global__ void k_last(const float* __restrict__ stds, float* __restrict__ out) {
    __shared__ float s_lp;
    if (threadIdx.x < 32) {
        float v = logf(10.0f * stds[threadIdx.x]);
#pragma unroll
        for (int o = 16; o > 0; o >>= 1) v += __shfl_down_sync(0xffffffffu, v, o);
        if (threadIdx.x == 0) s_lp = -v;
    }
    __syncthreads();
    int i = blockIdx.x * blockDim.x + threadIdx.x;
    int n = i >> 4, j = i & 15;
    float ladj = g_ladj[i];
    float x2;
    spline2_step(n, j, x2, ladj);
    float z1 = g_z[n * DD + j];
    float ss = fmaf(z1, z1, x2 * x2);
#pragma unroll
    for (int o = 1; o < 16; o <<= 1) {
        ss   += __shfl_xor_sync(0xffffffffu, ss, o);
        ladj += __shfl_xor_sync(0xffffffffu, ladj, o);
    }
    if ((threadIdx.x & 15) == 0)
        out[n] = -0.5f * ss - 0.5f * (float)DD * LOG2PI_F + ladj + s_lp;
}

// ================= HMMA fp16 GEMM (plain fp16 weights) =================
// CTA 128x128, 4 warps, warp tile 64x64. B stored [Npad,K] K-major fp16.
// smem: rows of 64 fp16, stride 144B (conflict-free ldmatrix). BK=64, 2 stages.
#define RSTR    144
#define TILE_B  (128 * RSTR)          // 18432
#define STAGE_B (2 * TILE_B)          // 36864 (A + B)
#define SM_TOTAL (2 * STAGE_B)        // 73728

template <bool RELU, bool F32OUT>
__global__ void __launch_bounds__(128) hgemm(
    const __half* __restrict__ A,
    const __half* __restrict__ B,
    const float* __restrict__ bias,
    int K, int Nreal, int ldc,
    __half* __restrict__ Ch, float* __restrict__ Cf)
{
    extern __shared__ char smem[];
    const uint32_t sb = smem_u32(smem);
    const int tid = threadIdx.x;
    const int wid = tid >> 5, lane = tid & 31;
    const int wm = wid >> 1, wn = wid & 1;          // 2x2 warp grid, warp tile 64x64

    const int brow = blockIdx.y * 128;
    const int bcol = blockIdx.x * 128;
    const int nch = K >> 6;

    float acc[4][8][4];
#pragma unroll
    for (int i = 0; i < 4; i++)
#pragma unroll
        for (int j = 0; j < 8; j++)
#pragma unroll
            for (int q = 0; q < 4; q++) acc[i][j][q] = 0.f;

    // 2048 16B units per chunk: A(1024) + B(1024); 16 per thread
    auto load_chunk = [&](int ch, int stage) {
        const int k0 = ch * 64;
        const uint32_t sbase = sb + stage * STAGE_B;
#pragma unroll
        for (int u = 0; u < 16; u++) {
            int idx = tid + u * 128;
            int mat = idx >> 10;
            int wi  = idx & 1023;
            int r = wi >> 3, c = wi & 7;
            uint32_t so = (uint32_t)(mat * TILE_B + r * RSTR + c * 16);
            const __half* src = (mat == 0) ? (A + (size_t)(brow + r) * K + k0 + c * 8)
                                           : (B + (size_t)(bcol + r) * K + k0 + c * 8);
            cp16(sbase + so, src);
        }
        asm volatile("cp.async.commit_group;" ::: "memory");
    };

    load_chunk(0, 0);

    for (int ch = 0; ch < nch; ch++) {
        if (ch + 1 < nch) {
            load_chunk(ch + 1, (ch + 1) & 1);
            asm volatile("cp.async.wait_group 1;" ::: "memory");
        } else {
            asm volatile("cp.async.wait_group 0;" ::: "memory");
        }
        __syncthreads();

        const uint32_t sbase = sb + (ch & 1) * STAGE_B;
        const uint32_t abase = sbase;
        const uint32_t bbase = sbase + TILE_B;

#pragma unroll
        for (int ks = 0; ks < 4; ks++) {
            uint32_t a[4][4];
            const uint32_t arow = (uint32_t)(wm * 64 + (lane & 15));
            const uint32_t akb  = (uint32_t)(ks * 32 + ((lane >> 4) & 1) * 16);
#pragma unroll
            for (int tm = 0; tm < 4; tm++) {
                uint32_t off = (arow + tm * 16) * RSTR + akb;
                ldsm4(a[tm][0], a[tm][1], a[tm][2], a[tm][3], abase + off);
            }
            uint32_t b_h[8][2];
            const uint32_t nrow0 = (uint32_t)(wn * 64 + (lane & 7) + ((lane >> 4) & 1) * 8);
            const uint32_t bkb   = (uint32_t)(ks * 32 + ((lane >> 3) & 1) * 16);
#pragma unroll
            for (int tp = 0; tp < 4; tp++) {
                uint32_t off = (nrow0 + tp * 16) * RSTR + bkb;
                ldsm4(b_h[tp * 2][0], b_h[tp * 2][1], b_h[tp * 2 + 1][0], b_h[tp * 2 + 1][1], bbase + off);
            }
#pragma unroll
            for (int tm = 0; tm < 4; tm++)
#pragma unroll
                for (int tn = 0; tn < 8; tn++)
                    mma_f16(acc[tm][tn], a[tm], b_h[tn]);
        }
        __syncthreads();
    }

    // epilogue: bias (+ReLU); fp16 activation or fp32 P output
#pragma unroll
    for (int tm = 0; tm < 4; tm++) {
#pragma unroll
        for (int tn = 0; tn < 8; tn++) {
            int n = bcol + wn * 64 + tn * 8 + 2 * (lane & 3);
            if (n >= Nreal) continue;
            float bb0 = bias[n], bb1 = bias[n + 1];
#pragma unroll
            for (int half = 0; half < 2; half++) {
                int m = brow + wm * 64 + tm * 16 + (lane >> 2) + half * 8;
                float v0 = acc[tm][tn][half * 2 + 0] + bb0;
                float v1 = acc[tm][tn][half * 2 + 1] + bb1;
                if (RELU) { v0 = fmaxf(v0, 0.f); v1 = fmaxf(v1, 0.f); }
                if (F32OUT) {
                    *reinterpret_cast<float2*>(Cf + (size_t)m * ldc + n) = make_float2(v0, v1);
                } else {
                    __half2 hv = __floats2half2_rn(v0, v1);
                    *reinterpret_cast<__half2*>(Ch + (size_t)m * ldc + n) = hv;
                }
            }
        }
    }
}

// ================= launch =================
extern "C" void kernel_launch(void* const* d_in, const int* in_sizes, int n_in,
                              void* d_out, int out_size) {
    const float* data  = (const float*)d_in[0];
    const float* means = (const float*)d_in[1];
    const float* stds  = (const float*)d_in[2];

    const float* tw[2]  = { (const float*)d_in[13], (const float*)d_in[3] };
    const float* th[2]  = { (const float*)d_in[14], (const float*)d_in[4] };
    const float* td[2]  = { (const float*)d_in[15], (const float*)d_in[5] };
    const float* tl[2]  = { (const float*)d_in[16], (const float*)d_in[6] };
    const float* tW1[2] = { (const float*)d_in[17], (const float*)d_in[7] };
    const float* tb1[2] = { (const float*)d_in[18], (const float*)d_in[8] };
    const float* tW2[2] = { (const float*)d_in[19], (const float*)d_in[9] };
    const float* tb2[2] = { (const float*)d_in[20], (const float*)d_in[10] };
    const float* tW3[2] = { (const float*)d_in[21], (const float*)d_in[11] };
    const float* tb3[2] = { (const float*)d_in[22], (const float*)d_in[12] };

    float* out = (float*)d_out;

    __half *x1, *H1, *H2, *W1t, *W2t, *W3t;
    float* pP;
    cudaGetSymbolAddress((void**)&x1,  g_x1);
    cudaGetSymbolAddress((void**)&H1,  g_H1);
    cudaGetSymbolAddress((void**)&H2,  g_H2);
    cudaGetSymbolAddress((void**)&W1t, g_W1t);
    cudaGetSymbolAddress((void**)&W2t, g_W2t);
    cudaGetSymbolAddress((void**)&W3t, g_W3t);
    cudaGetSymbolAddress((void**)&pP, g_P);

    cudaFuncSetAttribute(hgemm<true,  false>, cudaFuncAttributeMaxDynamicSharedMemorySize, SM_TOTAL);
    cudaFuncSetAttribute(hgemm<false, true >, cudaFuncAttributeMaxDynamicSharedMemorySize, SM_TOTAL);

    const int splineBlocks = (NS * SPLITD) / 256;
    dim3 g12(NP12 / 128, NS / 128);  // (3, 256)
    dim3 g3 (NP3  / 128, NS / 128);  // (8, 256)
    const int prepBlocks = (PREP_TOT + 255) / 256;

    for (int L = 0; L < 2; L++) {   // L=0 -> t2 (applied first), L=1 -> t1
        k_prepall<<<prepBlocks, 256>>>(tW1[L], tW2[L], tW3[L]);

        if (L == 0)
            k_first<<<splineBlocks, 256>>>(data, means, stds, tw[0], th[0], td[0], tl[0]);

        hgemm<true,  false><<<g12, 128, SM_TOTAL>>>(x1, W1t, tb1[L],
                                                    KP1, HID, HID, H1, nullptr);
        hgemm<true,  false><<<g12, 128, SM_TOTAL>>>(H1, W2t, tb2[L],
                                                    HID, HID, HID, H2, nullptr);
        hgemm<false, true ><<<g3,  128, SM_TOTAL>>>(H2, W3t, tb3[L],
                                                    HID, POUT, POUT, nullptr, pP);

        if (L == 0)
            k_mid<<<splineBlocks, 256>>>(tw[1], th[1], td[1], tl[1]);
        else
            k_last<<<splineBlocks, 256>>>(stds, out);
    }
}

// round 7
// speedup vs baseline: 4.9967x; 1.0018x over previous
#include <cuda_runtime.h>
#include <cuda_fp16.h>
#include <math.h>
#include <stdint.h>

#define NS    32768
#define DD    32
#define SPLITD 16
#define BINSN 16
#define HID   320
#define POUT  1008
#define LOG2PI_F 1.8378770664093453f

// padded GEMM dims
#define KP1   64      // GEMM1 K padded (real 16)
#define NP12  384     // GEMM1/2 N padded (real 320)
#define NP3   1024    // GEMM3 N padded (real 1008)

// ================= scratch (device globals; zero-initialized at load) =================
__device__ float g_z[NS * DD];
__device__ float g_ladj[NS * SPLITD];
__device__ __half g_P[(size_t)NS * POUT];

__device__ __half g_x1[NS * KP1];     // pad cols stay zero forever
__device__ __half g_H1[NS * HID];
__device__ __half g_H2[NS * HID];

__device__ __half g_W1t[NP12 * KP1];
__device__ __half g_W2t[NP12 * HID];
__device__ __half g_W3t[(size_t)NP3 * HID];

// ================= helpers =================
__device__ __forceinline__ uint32_t smem_u32(const void* p) {
    uint32_t a;
    asm("{ .reg .u64 t; cvta.to.shared.u64 t, %1; cvt.u32.u64 %0, t; }" : "=r"(a) : "l"(p));
    return a;
}
__device__ __forceinline__ void cp16(uint32_t dst, const void* src) {
    asm volatile("cp.async.cg.shared.global [%0], [%1], 16;" :: "r"(dst), "l"(src));
}
__device__ __forceinline__ void ldsm4(uint32_t& r0, uint32_t& r1, uint32_t& r2, uint32_t& r3, uint32_t a) {
    asm volatile("ldmatrix.sync.aligned.m8n8.x4.shared.b16 {%0,%1,%2,%3}, [%4];"
                 : "=r"(r0), "=r"(r1), "=r"(r2), "=r"(r3) : "r"(a));
}
__device__ __forceinline__ void mma_f16(float* c, const uint32_t* a, const uint32_t* b) {
    asm volatile("mma.sync.aligned.m16n8k16.row.col.f32.f16.f16.f32 "
                 "{%0,%1,%2,%3}, {%4,%5,%6,%7}, {%8,%9}, {%0,%1,%2,%3};"
                 : "+f"(c[0]), "+f"(c[1]), "+f"(c[2]), "+f"(c[3])
                 : "r"(a[0]), "r"(a[1]), "r"(a[2]), "r"(a[3]), "r"(b[0]), "r"(b[1]));
}
__device__ __forceinline__ float tof(float v) { return v; }
__device__ __forceinline__ float tof(__half v) { return __half2float(v); }

// ================= weight prep (one launch per layer) =================
#define SEG1 (NP12 * KP1)
#define SEG2 (NP12 * HID)
#define SEG3 (NP3 * HID)
#define PREP_TOT (SEG1 + SEG2 + SEG3)

__global__ void k_prepall(const float* __restrict__ W1, const float* __restrict__ W2,
                          const float* __restrict__ W3) {
    int idx = blockIdx.x * blockDim.x + threadIdx.x;
    const float* W; __half* T; int K, N, Kp;
    if (idx < SEG1)              { W = W1; T = g_W1t; K = SPLITD; N = HID;  Kp = KP1; }
    else if (idx < SEG1 + SEG2)  { idx -= SEG1; W = W2; T = g_W2t; K = HID; N = HID;  Kp = HID; }
    else if (idx < PREP_TOT)     { idx -= SEG1 + SEG2; W = W3; T = g_W3t; K = HID; N = POUT; Kp = HID; }
    else return;
    int n = idx / Kp, k = idx - n * Kp;
    float v = (n < N && k < K) ? W[(size_t)k * N + n] : 0.0f;
    T[idx] = __float2half_rn(v);
}

// ================= spline inverse (param type T = float or __half) =================
__device__ __forceinline__ float softplusf(float v) {
    return fmaxf(v, 0.0f) + log1pf(expf(-fabsf(v)));
}

template <typename T>
__device__ __forceinline__ void rls_inv(
    float y,
    const T* __restrict__ wr, const T* __restrict__ hr,
    const T* __restrict__ dr, const T* __restrict__ lr,
    float& xo, float& lo_)
{
    const float BD = 3.0f;
    float w[BINSN], h[BINSN];
#pragma unroll
    for (int b = 0; b < BINSN; b++) { w[b] = tof(wr[b]); h[b] = tof(hr[b]); }

    bool inside = (y >= -BD) && (y <= BD);
    float yc = fminf(fmaxf(y, -BD), BD);

    float hm = h[0];
#pragma unroll
    for (int b = 1; b < BINSN; b++) hm = fmaxf(hm, h[b]);
    float hs = 0.f;
#pragma unroll
    for (int b = 0; b < BINSN; b++) { h[b] = expf(h[b] - hm); hs += h[b]; }
    float hscale = 0.984f / hs;

    int idx = 0; float ich = -BD, ih = 0.f;
    {
        float prev = -BD, cs = 0.f;
#pragma unroll
        for (int b = 0; b < BINSN; b++) {
            float hb = 0.001f + hscale * h[b];
            cs += hb;
            float e = (b == BINSN - 1) ? BD : fmaf(6.0f, cs, -3.0f);
            if (yc >= prev) { idx = b; ich = prev; ih = e - prev; }
            prev = e;
        }
    }

    float wm = w[0];
#pragma unroll
    for (int b = 1; b < BINSN; b++) wm = fmaxf(wm, w[b]);
    float ws = 0.f;
#pragma unroll
    for (int b = 0; b < BINSN; b++) { w[b] = expf(w[b] - wm); ws += w[b]; }
    float wscale = 0.984f / ws;

    float icw = -BD, iw = 0.f;
    {
        float prev = -BD, cs = 0.f;
#pragma unroll
        for (int b = 0; b < BINSN; b++) {
            float wb_ = 0.001f + wscale * w[b];
            cs += wb_;
            float e = (b == BINSN - 1) ? BD : fmaf(6.0f, cs, -3.0f);
            if (b == idx) { icw = prev; iw = e - prev; }
            prev = e;
        }
    }

    float idv   = (idx == 0)         ? 0.999f : (0.001f + softplusf(tof(dr[idx - 1])));
    float idvp1 = (idx == BINSN - 1) ? 0.999f : (0.001f + softplusf(tof(dr[idx])));
    float il    = 0.025f + 0.95f / (1.0f + expf(-tof(lr[idx])));

    float idel = ih / iw;
    float wb   = sqrtf(idv / idvp1);
    float wc   = (il * idv + (1.0f - il) * wb * idvp1) / idel;
    float ya = ich, yb = ih + ich;
    float ym = ((1.0f - il) * ya + il * wb * yb) / ((1.0f - il) + il * wb);

    bool left = (yc <= ym);
    float num, den, dnum;
    if (left) {
        num  = il * (ya - yc);
        den  = (wc - 1.0f) * yc + ya - wc * ym;
        dnum = wc * il * (ym - ya) * iw;
    } else {
        num  = (wc - il * wb) * yc + il * wb * yb - wc * ym;
        den  = (wc - wb) * yc + wb * yb - wc * ym;
        dnum = wb * wc * (1.0f - il) * (yb - ym) * iw;
    }
    float x  = num / den * iw + icw;
    float la = logf(dnum) - 2.0f * logf(fabsf(den));

    xo  = inside ? x  : y;
    lo_ = inside ? la : 0.0f;
}

// spline2 on second half from P row (fp16); returns x2, accumulated ladj
__device__ __forceinline__ void spline2_step(int n, int j, float& x2, float& ladj_acc) {
    float y = g_z[n * DD + SPLITD + j];
    const __half* pr = g_P + (size_t)n * POUT;
    float la;
    rls_inv(y,
            pr + j * BINSN,
            pr + 256 + j * BINSN,
            pr + 512 + j * (BINSN - 1),
            pr + 752 + j * BINSN,
            x2, la);
    ladj_acc += la;
}

// first kernel: affine prelude + spline1 of layer 0
__global__ void k_first(const float* __restrict__ data,
                        const float* __restrict__ means,
                        const float* __restrict__ stds,
                        const float* __restrict__ wp, const float* __restrict__ hp,
                        const float* __restrict__ dp, const float* __restrict__ lp) {
    int i = blockIdx.x * blockDim.x + threadIdx.x;
    if (i >= NS * SPLITD) return;
    int n = i >> 4, j = i & 15;
    float y  = (data[n * DD + j]      - means[j])      / (10.0f * stds[j]);
    float y2 = (data[n * DD + j + 16] - means[j + 16]) / (10.0f * stds[j + 16]);
    g_z[n * DD + j + 16] = y2;
    float x, la;
    rls_inv(y, wp + j * BINSN, hp + j * BINSN, dp + j * (BINSN - 1), lp + j * BINSN, x, la);
    g_z[n * DD + j] = x;
    g_x1[n * KP1 + j] = __float2half_rn(x);
    g_ladj[i] = la;
}

// mid kernel: spline2 of layer L (from P) + spline1 of layer L+1 (fixed params)
__global__ void k_mid(const float* __restrict__ wp, const float* __restrict__ hp,
                      const float* __restrict__ dp, const float* __restrict__ lp) {
    int i = blockIdx.x * blockDim.x + threadIdx.x;
    if (i >= NS * SPLITD) return;
    int n = i >> 4, j = i & 15;
    float ladj = g_ladj[i];
    float x2;
    spline2_step(n, j, x2, ladj);
    g_z[n * DD + SPLITD + j] = x2;

    float y1 = g_z[n * DD + j];
    float x1, la1;
    rls_inv(y1, wp + j * BINSN, hp + j * BINSN, dp + j * (BINSN - 1), lp + j * BINSN, x1, la1);
    g_z[n * DD + j] = x1;
    g_x1[n * KP1 + j] = __float2half_rn(x1);
    g_ladj[i] = ladj + la1;
}

// last kernel: spline2 of final layer + Gaussian base + lpaff reduction -> out
__global__ void k_last(const float* __restrict__ stds, float* __restrict__ out) {
    __shared__ float s_lp;
    if (threadIdx.x < 32) {
        float v = logf(10.0f * stds[threadIdx.x]);
#pragma unroll
        for (int o = 16; o > 0; o >>= 1) v += __shfl_down_sync(0xffffffffu, v, o);
        if (threadIdx.x == 0) s_lp = -v;
    }
    __syncthreads();
    int i = blockIdx.x * blockDim.x + threadIdx.x;
    int n = i >> 4, j = i & 15;
    float ladj = g_ladj[i];
    float x2;
    spline2_step(n, j, x2, ladj);
    float z1 = g_z[n * DD + j];
    float ss = fmaf(z1, z1, x2 * x2);
#pragma unroll
    for (int o = 1; o < 16; o <<= 1) {
        ss   += __shfl_xor_sync(0xffffffffu, ss, o);
        ladj += __shfl_xor_sync(0xffffffffu, ladj, o);
    }
    if ((threadIdx.x & 15) == 0)
        out[n] = -0.5f * ss - 0.5f * (float)DD * LOG2PI_F + ladj + s_lp;
}

// ================= HMMA fp16 GEMM, 4-stage cp.async pipeline =================
// CTA 128x128, 8 warps (4x2), warp tile 32x64. B stored [Npad,K] K-major fp16.
// BK=32; smem rows of 32 fp16, stride 80B (conflict-free ldmatrix); 4 stages, 1 sync/chunk.
#define BK      32
#define RSTR    80
#define TILE_B  (128 * RSTR)          // 10240
#define STAGE_B (2 * TILE_B)          // 20480 (A + B)
#define NSTAGE  4
#define SM_TOTAL (NSTAGE * STAGE_B)   // 81920

template <bool RELU>
__global__ void __launch_bounds__(256) hgemm(
    const __half* __restrict__ A,
    const __half* __restrict__ B,
    const float* __restrict__ bias,
    int K, int Nreal, int ldc,
    __half* __restrict__ C)
{
    extern __shared__ char smem[];
    const uint32_t sb = smem_u32(smem);
    const int tid = threadIdx.x;
    const int wid = tid >> 5, lane = tid & 31;
    const int wm = wid >> 1, wn = wid & 1;          // 4x2 warp grid, warp tile 32x64

    const int brow = blockIdx.y * 128;
    const int bcol = blockIdx.x * 128;
    const int nch = K / BK;

    float acc[2][8][4];
#pragma unroll
    for (int i = 0; i < 2; i++)
#pragma unroll
        for (int j = 0; j < 8; j++)
#pragma unroll
            for (int q = 0; q < 4; q++) acc[i][j][q] = 0.f;

    // per chunk: A 128x32 + B 128x32 halves = 1024 16B units; 4 per thread
    auto load_chunk = [&](int ch, int stage) {
        const int k0 = ch * BK;
        const uint32_t sbase = sb + stage * STAGE_B;
#pragma unroll
        for (int u = 0; u < 4; u++) {
            int idx = tid + u * 256;
            int mat = idx >> 9;
            int wi  = idx & 511;
            int r = wi >> 2, c = wi & 3;
            uint32_t so = (uint32_t)(mat * TILE_B + r * RSTR + c * 16);
            const __half* src = (mat == 0) ? (A + (size_t)(brow + r) * K + k0 + c * 8)
                                           : (B + (size_t)(bcol + r) * K + k0 + c * 8);
            cp16(sbase + so, src);
        }
        asm volatile("cp.async.commit_group;" ::: "memory");
    };

    // prologue: fill up to NSTAGE-1 stages
    const int pre = (nch < NSTAGE - 1) ? nch : (NSTAGE - 1);
    for (int s = 0; s < pre; s++) load_chunk(s, s);

    for (int ch = 0; ch < nch; ch++) {
        const int rem = nch - 1 - ch;
        if (rem >= 2)      asm volatile("cp.async.wait_group 2;" ::: "memory");
        else if (rem == 1) asm volatile("cp.async.wait_group 1;" ::: "memory");
        else               asm volatile("cp.async.wait_group 0;" ::: "memory");
        __syncthreads();

        const int nx = ch + NSTAGE - 1;
        if (nx < nch) load_chunk(nx, nx & (NSTAGE - 1));

        const uint32_t sbase = sb + (ch & (NSTAGE - 1)) * STAGE_B;
        const uint32_t abase = sbase;
        const uint32_t bbase = sbase + TILE_B;

#pragma unroll
        for (int ks = 0; ks < 2; ks++) {
            uint32_t a[2][4];
            const uint32_t arow = (uint32_t)(wm * 32 + (lane & 15));
            const uint32_t akb  = (uint32_t)(ks * 32 + ((lane >> 4) & 1) * 16);
#pragma unroll
            for (int tm = 0; tm < 2; tm++) {
                uint32_t off = (arow + tm * 16) * RSTR + akb;
                ldsm4(a[tm][0], a[tm][1], a[tm][2], a[tm][3], abase + off);
            }
            uint32_t bf[8][2];
            const uint32_t nrow0 = (uint32_t)(wn * 64 + (lane & 7) + ((lane >> 4) & 1) * 8);
            const uint32_t bkb   = (uint32_t)(ks * 32 + ((lane >> 3) & 1) * 16);
#pragma unroll
            for (int tp = 0; tp < 4; tp++) {
                uint32_t off = (nrow0 + tp * 16) * RSTR + bkb;
                ldsm4(bf[tp * 2][0], bf[tp * 2][1], bf[tp * 2 + 1][0], bf[tp * 2 + 1][1], bbase + off);
            }
#pragma unroll
            for (int tm = 0; tm < 2; tm++)
#pragma unroll
                for (int tn = 0; tn < 8; tn++)
                    mma_f16(acc[tm][tn], a[tm], bf[tn]);
        }
    }

    // epilogue: bias (+ReLU), fp16 output
#pragma unroll
    for (int tm = 0; tm < 2; tm++) {
#pragma unroll
        for (int tn = 0; tn < 8; tn++) {
            int n = bcol + wn * 64 + tn * 8 + 2 * (lane & 3);
            if (n >= Nreal) continue;
            float bb0 = bias[n], bb1 = bias[n + 1];
#pragma unroll
            for (int half = 0; half < 2; half++) {
                int m = brow + wm * 32 + tm * 16 + (lane >> 2) + half * 8;
                float v0 = acc[tm][tn][half * 2 + 0] + bb0;
                float v1 = acc[tm][tn][half * 2 + 1] + bb1;
                if (RELU) { v0 = fmaxf(v0, 0.f); v1 = fmaxf(v1, 0.f); }
                __half2 hv = __floats2half2_rn(v0, v1);
                *reinterpret_cast<__half2*>(C + (size_t)m * ldc + n) = hv;
            }
        }
    }
}

// ================= launch =================
extern "C" void kernel_launch(void* const* d_in, const int* in_sizes, int n_in,
                              void* d_out, int out_size) {
    const float* data  = (const float*)d_in[0];
    const float* means = (const float*)d_in[1];
    const float* stds  = (const float*)d_in[2];

    const float* tw[2]  = { (const float*)d_in[13], (const float*)d_in[3] };
    const float* th[2]  = { (const float*)d_in[14], (const float*)d_in[4] };
    const float* td[2]  = { (const float*)d_in[15], (const float*)d_in[5] };
    const float* tl[2]  = { (const float*)d_in[16], (const float*)d_in[6] };
    const float* tW1[2] = { (const float*)d_in[17], (const float*)d_in[7] };
    const float* tb1[2] = { (const float*)d_in[18], (const float*)d_in[8] };
    const float* tW2[2] = { (const float*)d_in[19], (const float*)d_in[9] };
    const float* tb2[2] = { (const float*)d_in[20], (const float*)d_in[10] };
    const float* tW3[2] = { (const float*)d_in[21], (const float*)d_in[11] };
    const float* tb3[2] = { (const float*)d_in[22], (const float*)d_in[12] };

    float* out = (float*)d_out;

    __half *x1, *H1, *H2, *W1t, *W2t, *W3t, *pP;
    cudaGetSymbolAddress((void**)&x1,  g_x1);
    cudaGetSymbolAddress((void**)&H1,  g_H1);
    cudaGetSymbolAddress((void**)&H2,  g_H2);
    cudaGetSymbolAddress((void**)&W1t, g_W1t);
    cudaGetSymbolAddress((void**)&W2t, g_W2t);
    cudaGetSymbolAddress((void**)&W3t, g_W3t);
    cudaGetSymbolAddress((void**)&pP,  g_P);

    cudaFuncSetAttribute(hgemm<true >, cudaFuncAttributeMaxDynamicSharedMemorySize, SM_TOTAL);
    cudaFuncSetAttribute(hgemm<false>, cudaFuncAttributeMaxDynamicSharedMemorySize, SM_TOTAL);

    const int splineBlocks = (NS * SPLITD) / 256;
    dim3 g12(NP12 / 128, NS / 128);  // (3, 256)
    dim3 g3 (NP3  / 128, NS / 128);  // (8, 256)
    const int prepBlocks = (PREP_TOT + 255) / 256;

    for (int L = 0; L < 2; L++) {   // L=0 -> t2 (applied first), L=1 -> t1
        k_prepall<<<prepBlocks, 256>>>(tW1[L], tW2[L], tW3[L]);

        if (L == 0)
            k_first<<<splineBlocks, 256>>>(data, means, stds, tw[0], th[0], td[0], tl[0]);

        hgemm<true ><<<g12, 256, SM_TOTAL>>>(x1, W1t, tb1[L], KP1, HID, HID, H1);
        hgemm<true ><<<g12, 256, SM_TOTAL>>>(H1, W2t, tb2[L], HID, HID, HID, H2);
        hgemm<false><<<g3,  256, SM_TOTAL>>>(H2, W3t, tb3[L], HID, POUT, POUT, pP);

        if (L == 0)
            k_mid<<<splineBlocks, 256>>>(tw[1], th[1], td[1], tl[1]);
        else
            k_last<<<splineBlocks, 256>>>(stds, out);
    }
}

// round 8
// speedup vs baseline: 5.7169x; 1.1441x over previous
#include <cuda_runtime.h>
#include <cuda_fp16.h>
#include <math.h>
#include <stdint.h>

#define NS    32768
#define DD    32
#define SPLITD 16
#define BINSN 16
#define HID   320
#define POUT  1008
#define LOG2PI_F 1.8378770664093453f

// padded GEMM dims
#define KP1   64      // GEMM1 K padded (real 16)
#define NP12  384     // GEMM1/2 N padded (real 320)
#define NP3   1024    // GEMM3 N padded (real 1008)

// ================= scratch (device globals; zero-initialized at load) =================
__device__ float g_z[NS * DD];
__device__ float g_ladj[NS * SPLITD];
__device__ __half g_P[(size_t)NS * POUT];

__device__ __half g_x1[NS * KP1];     // pad cols stay zero forever
__device__ __half g_H1[NS * HID];
__device__ __half g_H2[NS * HID];

__device__ __half g_W1t[2][NP12 * KP1];
__device__ __half g_W2t[2][NP12 * HID];
__device__ __half g_W3t[2][(size_t)NP3 * HID];

// spline1 tables: [layer][dim][bin]
__device__ float g_sknot[2][SPLITD][16];        // left knot of each bin (height space)
__device__ float g_sbin[2][SPLITD][BINSN][12];  // ya yb ym iw icw il wb wc dnl dnr pad pad

// ================= helpers =================
__device__ __forceinline__ uint32_t smem_u32(const void* p) {
    uint32_t a;
    asm("{ .reg .u64 t; cvta.to.shared.u64 t, %1; cvt.u32.u64 %0, t; }" : "=r"(a) : "l"(p));
    return a;
}
__device__ __forceinline__ void cp16(uint32_t dst, const void* src) {
    asm volatile("cp.async.cg.shared.global [%0], [%1], 16;" :: "r"(dst), "l"(src));
}
__device__ __forceinline__ void ldsm4(uint32_t& r0, uint32_t& r1, uint32_t& r2, uint32_t& r3, uint32_t a) {
    asm volatile("ldmatrix.sync.aligned.m8n8.x4.shared.b16 {%0,%1,%2,%3}, [%4];"
                 : "=r"(r0), "=r"(r1), "=r"(r2), "=r"(r3) : "r"(a));
}
__device__ __forceinline__ void mma_f16(float* c, const uint32_t* a, const uint32_t* b) {
    asm volatile("mma.sync.aligned.m16n8k16.row.col.f32.f16.f16.f32 "
                 "{%0,%1,%2,%3}, {%4,%5,%6,%7}, {%8,%9}, {%0,%1,%2,%3};"
                 : "+f"(c[0]), "+f"(c[1]), "+f"(c[2]), "+f"(c[3])
                 : "r"(a[0]), "r"(a[1]), "r"(a[2]), "r"(a[3]), "r"(b[0]), "r"(b[1]));
}
__device__ __forceinline__ float tof(__half v) { return __half2float(v); }

// ================= weight prep: BOTH layers in one launch =================
#define SEG1 (NP12 * KP1)
#define SEG2 (NP12 * HID)
#define SEG3 (NP3 * HID)
#define PREP_TOT (SEG1 + SEG2 + SEG3)

__global__ void k_prepall(const float* __restrict__ W1a, const float* __restrict__ W2a,
                          const float* __restrict__ W3a,
                          const float* __restrict__ W1b, const float* __restrict__ W2b,
                          const float* __restrict__ W3b) {
    int gi = blockIdx.x * blockDim.x + threadIdx.x;
    int L = (gi >= PREP_TOT) ? 1 : 0;
    int idx = gi - L * PREP_TOT;
    if (idx >= PREP_TOT) return;
    const float* W; __half* T; int K, N, Kp;
    if (idx < SEG1)              { W = L ? W1b : W1a; T = g_W1t[L]; K = SPLITD; N = HID;  Kp = KP1; }
    else if (idx < SEG1 + SEG2)  { idx -= SEG1; W = L ? W2b : W2a; T = g_W2t[L] - SEG1; K = HID; N = HID;  Kp = HID; }
    else                         { idx -= SEG1 + SEG2; W = L ? W3b : W3a; T = g_W3t[L] - SEG1 - SEG2; K = HID; N = POUT; Kp = HID; }
    // note: T offset trick keeps T[idx0] addressing; recompute cleanly:
    int idx0 = (gi - L * PREP_TOT);
    if (idx0 < SEG1) {
        int n = idx0 / KP1, k = idx0 - n * KP1;
        float v = (k < SPLITD) ? W[(size_t)k * HID + n] : 0.0f;   // n < HID always (NP12>HID pads)
        if (n >= HID) v = 0.0f;
        g_W1t[L][idx0] = __float2half_rn(v);
    } else if (idx0 < SEG1 + SEG2) {
        int i2 = idx0 - SEG1;
        int n = i2 / HID, k = i2 - n * HID;
        float v = (n < HID) ? ((const float*)(L ? W2b : W2a))[(size_t)k * HID + n] : 0.0f;
        g_W2t[L][i2] = __float2half_rn(v);
    } else {
        int i3 = idx0 - SEG1 - SEG2;
        int n = i3 / HID, k = i3 - n * HID;
        float v = (n < POUT) ? ((const float*)(L ? W3b : W3a))[(size_t)k * POUT + n] : 0.0f;
        g_W3t[L][i3] = __float2half_rn(v);
    }
}

// ================= spline1 table precompute (1 block, 512 threads) =================
__device__ __forceinline__ float softplus_fast(float v) {
    return fmaxf(v, 0.0f) + __logf(1.0f + __expf(-fabsf(v)));
}

__global__ void k_prepspline(const float* __restrict__ w0, const float* __restrict__ h0,
                             const float* __restrict__ d0, const float* __restrict__ l0,
                             const float* __restrict__ w1, const float* __restrict__ h1,
                             const float* __restrict__ d1, const float* __restrict__ l1) {
    int t = threadIdx.x;            // 0..511
    int L = t >> 8, j = (t >> 4) & 15, b = t & 15;
    const float* wr = (L ? w1 : w0) + j * BINSN;
    const float* hr = (L ? h1 : h0) + j * BINSN;
    const float* dr = (L ? d1 : d0) + j * (BINSN - 1);
    const float* lr = (L ? l1 : l0) + j * BINSN;

    float w[BINSN], h[BINSN];
#pragma unroll
    for (int k = 0; k < BINSN; k++) { w[k] = wr[k]; h[k] = hr[k]; }
    float hm = h[0], wm = w[0];
#pragma unroll
    for (int k = 1; k < BINSN; k++) { hm = fmaxf(hm, h[k]); wm = fmaxf(wm, w[k]); }
    float hs = 0.f, ws = 0.f;
#pragma unroll
    for (int k = 0; k < BINSN; k++) { h[k] = __expf(h[k] - hm); hs += h[k];
                                      w[k] = __expf(w[k] - wm); ws += w[k]; }
    float hscale = 0.984f / hs, wscale = 0.984f / ws;

    float ich = -3.f, ih = 0.f, icw = -3.f, iw = 0.f;
    {
        float prev = -3.f, cs = 0.f;
#pragma unroll
        for (int k = 0; k < BINSN; k++) {
            float hb = 0.001f + hscale * h[k];
            cs += hb;
            float e = (k == BINSN - 1) ? 3.f : fmaf(6.0f, cs, -3.0f);
            if (k == b) { ich = prev; ih = e - prev; }
            prev = e;
        }
    }
    {
        float prev = -3.f, cs = 0.f;
#pragma unroll
        for (int k = 0; k < BINSN; k++) {
            float wb_ = 0.001f + wscale * w[k];
            cs += wb_;
            float e = (k == BINSN - 1) ? 3.f : fmaf(6.0f, cs, -3.0f);
            if (k == b) { icw = prev; iw = e - prev; }
            prev = e;
        }
    }

    float idv   = (b == 0)         ? 0.999f : (0.001f + softplus_fast(dr[b - 1]));
    float idvp1 = (b == BINSN - 1) ? 0.999f : (0.001f + softplus_fast(dr[b]));
    float il    = 0.025f + 0.95f / (1.0f + __expf(-lr[b]));

    float idel = ih / iw;
    float wb   = sqrtf(idv / idvp1);
    float wc   = (il * idv + (1.0f - il) * wb * idvp1) / idel;
    float ya = ich, yb = ih + ich;
    float ym = ((1.0f - il) * ya + il * wb * yb) / ((1.0f - il) + il * wb);
    float dnl = wc * il * (ym - ya) * iw;
    float dnr = wb * wc * (1.0f - il) * (yb - ym) * iw;

    g_sknot[L][j][b] = ich;
    float* e = &g_sbin[L][j][b][0];
    e[0] = ya; e[1] = yb; e[2] = ym; e[3] = iw; e[4] = icw;
    e[5] = il; e[6] = wb; e[7] = wc; e[8] = dnl; e[9] = dnr;
}

// table-driven spline1 eval
__device__ __forceinline__ void spline1_tab(int L, int j, float y, float& xo, float& lo_) {
    bool inside = (y >= -3.f) && (y <= 3.f);
    float yc = fminf(fmaxf(y, -3.f), 3.f);
    const float* kn = &g_sknot[L][j][0];
    int idx = -1;
#pragma unroll
    for (int k = 0; k < 16; k++) idx += (yc >= kn[k]) ? 1 : 0;
    idx = (idx < 0) ? 0 : idx;
    const float* e = &g_sbin[L][j][idx][0];
    float4 e0 = *reinterpret_cast<const float4*>(e);
    float4 e1 = *reinterpret_cast<const float4*>(e + 4);
    float2 e2 = *reinterpret_cast<const float2*>(e + 8);
    float ya = e0.x, yb = e0.y, ym = e0.z, iw = e0.w;
    float icw = e1.x, il = e1.y, wb = e1.z, wc = e1.w;
    bool left = (yc <= ym);
    float num, den, dn;
    if (left) {
        num = il * (ya - yc);
        den = (wc - 1.0f) * yc + ya - wc * ym;
        dn  = e2.x;
    } else {
        num = (wc - il * wb) * yc + il * wb * yb - wc * ym;
        den = (wc - wb) * yc + wb * yb - wc * ym;
        dn  = e2.y;
    }
    float x  = num / den * iw + icw;
    float la = __logf(dn) - 2.0f * __logf(fabsf(den));
    xo  = inside ? x  : y;
    lo_ = inside ? la : 0.0f;
}

// full per-sample spline inverse (fp16 params from P), fast-math
__device__ __forceinline__ void rls_inv_h(
    float y,
    const __half* __restrict__ wr, const __half* __restrict__ hr,
    const __half* __restrict__ dr, const __half* __restrict__ lr,
    float& xo, float& lo_)
{
    const float BD = 3.0f;
    float w[BINSN], h[BINSN];
#pragma unroll
    for (int b = 0; b < BINSN; b++) { w[b] = tof(wr[b]); h[b] = tof(hr[b]); }

    bool inside = (y >= -BD) && (y <= BD);
    float yc = fminf(fmaxf(y, -BD), BD);

    float hm = h[0], wm = w[0];
#pragma unroll
    for (int b = 1; b < BINSN; b++) { hm = fmaxf(hm, h[b]); wm = fmaxf(wm, w[b]); }
    float hs = 0.f, ws = 0.f;
#pragma unroll
    for (int b = 0; b < BINSN; b++) { h[b] = __expf(h[b] - hm); hs += h[b];
                                      w[b] = __expf(w[b] - wm); ws += w[b]; }
    float hscale = 0.984f / hs;
    float wscale = 0.984f / ws;

    int idx = 0; float ich = -BD, ih = 0.f;
    {
        float prev = -BD, cs = 0.f;
#pragma unroll
        for (int b = 0; b < BINSN; b++) {
            float hb = 0.001f + hscale * h[b];
            cs += hb;
            float e = (b == BINSN - 1) ? BD : fmaf(6.0f, cs, -3.0f);
            if (yc >= prev) { idx = b; ich = prev; ih = e - prev; }
            prev = e;
        }
    }
    float icw = -BD, iw = 0.f;
    {
        float prev = -BD, cs = 0.f;
#pragma unroll
        for (int b = 0; b < BINSN; b++) {
            float wb_ = 0.001f + wscale * w[b];
            cs += wb_;
            float e = (b == BINSN - 1) ? BD : fmaf(6.0f, cs, -3.0f);
            if (b == idx) { icw = prev; iw = e - prev; }
            prev = e;
        }
    }

    float idv   = (idx == 0)         ? 0.999f : (0.001f + softplus_fast(tof(dr[idx - 1])));
    float idvp1 = (idx == BINSN - 1) ? 0.999f : (0.001f + softplus_fast(tof(dr[idx])));
    float il    = 0.025f + 0.95f / (1.0f + __expf(-tof(lr[idx])));

    float idel = ih / iw;
    float wb   = sqrtf(idv / idvp1);
    float wc   = (il * idv + (1.0f - il) * wb * idvp1) / idel;
    float ya = ich, yb = ih + ich;
    float ym = ((1.0f - il) * ya + il * wb * yb) / ((1.0f - il) + il * wb);

    bool left = (yc <= ym);
    float num, den, dnum;
    if (left) {
        num  = il * (ya - yc);
        den  = (wc - 1.0f) * yc + ya - wc * ym;
        dnum = wc * il * (ym - ya) * iw;
    } else {
        num  = (wc - il * wb) * yc + il * wb * yb - wc * ym;
        den  = (wc - wb) * yc + wb * yb - wc * ym;
        dnum = wb * wc * (1.0f - il) * (yb - ym) * iw;
    }
    float x  = num / den * iw + icw;
    float la = __logf(dnum) - 2.0f * __logf(fabsf(den));

    xo  = inside ? x  : y;
    lo_ = inside ? la : 0.0f;
}

__device__ __forceinline__ void spline2_step(int n, int j, float& x2, float& ladj_acc) {
    float y = g_z[n * DD + SPLITD + j];
    const __half* pr = g_P + (size_t)n * POUT;
    float la;
    rls_inv_h(y,
              pr + j * BINSN,
              pr + 256 + j * BINSN,
              pr + 512 + j * (BINSN - 1),
              pr + 752 + j * BINSN,
              x2, la);
    ladj_acc += la;
}

// first kernel: affine prelude + table spline1 of layer 0
__global__ void k_first(const float* __restrict__ data,
                        const float* __restrict__ means,
                        const float* __restrict__ stds) {
    int i = blockIdx.x * blockDim.x + threadIdx.x;
    if (i >= NS * SPLITD) return;
    int n = i >> 4, j = i & 15;
    float y  = (data[n * DD + j]      - means[j])      / (10.0f * stds[j]);
    float y2 = (data[n * DD + j + 16] - means[j + 16]) / (10.0f * stds[j + 16]);
    g_z[n * DD + j + 16] = y2;
    float x, la;
    spline1_tab(0, j, y, x, la);
    g_z[n * DD + j] = x;
    g_x1[n * KP1 + j] = __float2half_rn(x);
    g_ladj[i] = la;
}

// mid kernel: spline2 of layer 0 (per-sample) + table spline1 of layer 1
__global__ void k_mid() {
    int i = blockIdx.x * blockDim.x + threadIdx.x;
    if (i >= NS * SPLITD) return;
    int n = i >> 4, j = i & 15;
    float ladj = g_ladj[i];
    float x2;
    spline2_step(n, j, x2, ladj);
    g_z[n * DD + SPLITD + j] = x2;

    float y1 = g_z[n * DD + j];
    float x1, la1;
    spline1_tab(1, j, y1, x1, la1);
    g_z[n * DD + j] = x1;
    g_x1[n * KP1 + j] = __float2half_rn(x1);
    g_ladj[i] = ladj + la1;
}

// last kernel: spline2 of final layer + Gaussian base + lpaff reduction -> out
__global__ void k_last(const float* __restrict__ stds, float* __restrict__ out) {
    __shared__ float s_lp;
    if (threadIdx.x < 32) {
        float v = logf(10.0f * stds[threadIdx.x]);
#pragma unroll
        for (int o = 16; o > 0; o >>= 1) v += __shfl_down_sync(0xffffffffu, v, o);
        if (threadIdx.x == 0) s_lp = -v;
    }
    __syncthreads();
    int i = blockIdx.x * blockDim.x + threadIdx.x;
    int n = i >> 4, j = i & 15;
    float ladj = g_ladj[i];
    float x2;
    spline2_step(n, j, x2, ladj);
    float z1 = g_z[n * DD + j];
    float ss = fmaf(z1, z1, x2 * x2);
#pragma unroll
    for (int o = 1; o < 16; o <<= 1) {
        ss   += __shfl_xor_sync(0xffffffffu, ss, o);
        ladj += __shfl_xor_sync(0xffffffffu, ladj, o);
    }
    if ((threadIdx.x & 15) == 0)
        out[n] = -0.5f * ss - 0.5f * (float)DD * LOG2PI_F + ladj + s_lp;
}

// ================= HMMA fp16 GEMM (R6 config: BK=64, 4 warps, 64x64 tiles) =========
#define RSTR    144
#define TILE_B  (128 * RSTR)          // 18432
#define STAGE_B (2 * TILE_B)          // 36864 (A + B)
#define SM_TOTAL (2 * STAGE_B)        // 73728

template <bool RELU>
__global__ void __launch_bounds__(128) hgemm(
    const __half* __restrict__ A,
    const __half* __restrict__ B,
    const float* __restrict__ bias,
    int K, int Nreal, int ldc,
    __half* __restrict__ C)
{
    extern __shared__ char smem[];
    const uint32_t sb = smem_u32(smem);
    const int tid = threadIdx.x;
    const int wid = tid >> 5, lane = tid & 31;
    const int wm = wid >> 1, wn = wid & 1;          // 2x2 warp grid, warp tile 64x64

    const int brow = blockIdx.y * 128;
    const int bcol = blockIdx.x * 128;
    const int nch = K >> 6;

    float acc[4][8][4];
#pragma unroll
    for (int i = 0; i < 4; i++)
#pragma unroll
        for (int j = 0; j < 8; j++)
#pragma unroll
            for (int q = 0; q < 4; q++) acc[i][j][q] = 0.f;

    auto load_chunk = [&](int ch, int stage) {
        const int k0 = ch * 64;
        const uint32_t sbase = sb + stage * STAGE_B;
#pragma unroll
        for (int u = 0; u < 16; u++) {
            int idx = tid + u * 128;
            int mat = idx >> 10;
            int wi  = idx & 1023;
            int r = wi >> 3, c = wi & 7;
            uint32_t so = (uint32_t)(mat * TILE_B + r * RSTR + c * 16);
            const __half* src = (mat == 0) ? (A + (size_t)(brow + r) * K + k0 + c * 8)
                                           : (B + (size_t)(bcol + r) * K + k0 + c * 8);
            cp16(sbase + so, src);
        }
        asm volatile("cp.async.commit_group;" ::: "memory");
    };

    load_chunk(0, 0);

    for (int ch = 0; ch < nch; ch++) {
        if (ch + 1 < nch) {
            load_chunk(ch + 1, (ch + 1) & 1);
            asm volatile("cp.async.wait_group 1;" ::: "memory");
        } else {
            asm volatile("cp.async.wait_group 0;" ::: "memory");
        }
        __syncthreads();

        const uint32_t sbase = sb + (ch & 1) * STAGE_B;
        const uint32_t abase = sbase;
        const uint32_t bbase = sbase + TILE_B;

#pragma unroll
        for (int ks = 0; ks < 4; ks++) {
            uint32_t a[4][4];
            const uint32_t arow = (uint32_t)(wm * 64 + (lane & 15));
            const uint32_t akb  = (uint32_t)(ks * 32 + ((lane >> 4) & 1) * 16);
#pragma unroll
            for (int tm = 0; tm < 4; tm++) {
                uint32_t off = (arow + tm * 16) * RSTR + akb;
                ldsm4(a[tm][0], a[tm][1], a[tm][2], a[tm][3], abase + off);
            }
            uint32_t bf[8][2];
            const uint32_t nrow0 = (uint32_t)(wn * 64 + (lane & 7) + ((lane >> 4) & 1) * 8);
            const uint32_t bkb   = (uint32_t)(ks * 32 + ((lane >> 3) & 1) * 16);
#pragma unroll
            for (int tp = 0; tp < 4; tp++) {
                uint32_t off = (nrow0 + tp * 16) * RSTR + bkb;
                ldsm4(bf[tp * 2][0], bf[tp * 2][1], bf[tp * 2 + 1][0], bf[tp * 2 + 1][1], bbase + off);
            }
#pragma unroll
            for (int tm = 0; tm < 4; tm++)
#pragma unroll
                for (int tn = 0; tn < 8; tn++)
                    mma_f16(acc[tm][tn], a[tm], bf[tn]);
        }
        __syncthreads();
    }

#pragma unroll
    for (int tm = 0; tm < 4; tm++) {
#pragma unroll
        for (int tn = 0; tn < 8; tn++) {
            int n = bcol + wn * 64 + tn * 8 + 2 * (lane & 3);
            if (n >= Nreal) continue;
            float bb0 = bias[n], bb1 = bias[n + 1];
#pragma unroll
            for (int half = 0; half < 2; half++) {
                int m = brow + wm * 64 + tm * 16 + (lane >> 2) + half * 8;
                float v0 = acc[tm][tn][half * 2 + 0] + bb0;
                float v1 = acc[tm][tn][half * 2 + 1] + bb1;
                if (RELU) { v0 = fmaxf(v0, 0.f); v1 = fmaxf(v1, 0.f); }
                __half2 hv = __floats2half2_rn(v0, v1);
                *reinterpret_cast<__half2*>(C + (size_t)m * ldc + n) = hv;
            }
        }
    }
}

// ================= launch =================
extern "C" void kernel_launch(void* const* d_in, const int* in_sizes, int n_in,
                              void* d_out, int out_size) {
    const float* data  = (const float*)d_in[0];
    const float* means = (const float*)d_in[1];
    const float* stds  = (const float*)d_in[2];

    // slot 0 = t2 (applied first), slot 1 = t1
    const float* tw[2]  = { (const float*)d_in[13], (const float*)d_in[3] };
    const float* th[2]  = { (const float*)d_in[14], (const float*)d_in[4] };
    const float* td[2]  = { (const float*)d_in[15], (const float*)d_in[5] };
    const float* tl[2]  = { (const float*)d_in[16], (const float*)d_in[6] };
    const float* tW1[2] = { (const float*)d_in[17], (const float*)d_in[7] };
    const float* tb1[2] = { (const float*)d_in[18], (const float*)d_in[8] };
    const float* tW2[2] = { (const float*)d_in[19], (const float*)d_in[9] };
    const float* tb2[2] = { (const float*)d_in[20], (const float*)d_in[10] };
    const float* tW3[2] = { (const float*)d_in[21], (const float*)d_in[11] };
    const float* tb3[2] = { (const float*)d_in[22], (const float*)d_in[12] };

    float* out = (float*)d_out;

    __half *x1, *H1, *H2, *pP;
    __half *W1t0, *W2t0, *W3t0;
    cudaGetSymbolAddress((void**)&x1,  g_x1);
    cudaGetSymbolAddress((void**)&H1,  g_H1);
    cudaGetSymbolAddress((void**)&H2,  g_H2);
    cudaGetSymbolAddress((void**)&pP,  g_P);
    cudaGetSymbolAddress((void**)&W1t0, g_W1t);
    cudaGetSymbolAddress((void**)&W2t0, g_W2t);
    cudaGetSymbolAddress((void**)&W3t0, g_W3t);

    cudaFuncSetAttribute(hgemm<true >, cudaFuncAttributeMaxDynamicSharedMemorySize, SM_TOTAL);
    cudaFuncSetAttribute(hgemm<false>, cudaFuncAttributeMaxDynamicSharedMemorySize, SM_TOTAL);

    const int splineBlocks = (NS * SPLITD) / 256;
    dim3 g12(NP12 / 128, NS / 128);  // (3, 256)
    dim3 g3 (NP3  / 128, NS / 128);  // (8, 256)

    k_prepall<<<(2 * PREP_TOT + 255) / 256, 256>>>(tW1[0], tW2[0], tW3[0],
                                                   tW1[1], tW2[1], tW3[1]);
    k_prepspline<<<1, 512>>>(tw[0], th[0], td[0], tl[0], tw[1], th[1], td[1], tl[1]);

    k_first<<<splineBlocks, 256>>>(data, means, stds);

    for (int L = 0; L < 2; L++) {
        __half* W1t = W1t0 + (size_t)L * SEG1;
        __half* W2t = W2t0 + (size_t)L * SEG2;
        __half* W3t = W3t0 + (size_t)L * SEG3;

        hgemm<true ><<<g12, 128, SM_TOTAL>>>(x1, W1t, tb1[L], KP1, HID, HID, H1);
        hgemm<true ><<<g12, 128, SM_TOTAL>>>(H1, W2t, tb2[L], HID, HID, HID, H2);
        hgemm<false><<<g3,  128, SM_TOTAL>>>(H2, W3t, tb3[L], HID, POUT, POUT, pP);

        if (L == 0)
            k_mid<<<splineBlocks, 256>>>();
        else
            k_last<<<splineBlocks, 256>>>(stds, out);
    }
}